// round 2
// baseline (speedup 1.0000x reference)
#include <cuda_runtime.h>
#include <cuda_bf16.h>
#include <cstdint>

#define BB  4
#define NN  2048
#define FIN 256
#define HH  8
#define DD  32
#define NW  (NN/32)   // 64 adj words per row

// ---------------- device scratch (no allocations allowed) ----------------
__device__ float    g_Wh[BB*HH*NN*DD];     // [b][h][n][d]  8.4MB
__device__ float    g_esrc[BB*HH*NN];
__device__ float    g_edst[BB*HH*NN];
__device__ float4   g_AI[BB*HH*NN];        // (-e_src, A1, A2, 0)
__device__ float4   g_EJ[BB*HH*NN];        // (e_dst,  E1, E2, 0)
__device__ unsigned g_maxE[BB*HH];
__device__ unsigned g_adj[BB*NN*NW];       // packed adjacency bits, 2MB

// ---------------- f32x2 packed-FMA helpers (sm_103a) ----------------
__device__ __forceinline__ void ffma2(unsigned long long &acc,
                                      unsigned long long a, unsigned long long b) {
    asm("fma.rn.f32x2 %0, %1, %2, %0;" : "+l"(acc) : "l"(a), "l"(b));
}
__device__ __forceinline__ unsigned long long pk2(float lo, float hi) {
    unsigned long long r;
    asm("mov.b64 %0, {%1, %2};" : "=l"(r) : "f"(lo), "f"(hi));
    return r;
}
__device__ __forceinline__ float2 upk2(unsigned long long v) {
    float2 r;
    asm("mov.b64 {%0, %1}, %2;" : "=f"(r.x), "=f"(r.y) : "l"(v));
    return r;
}

// ---------------- kernel 1: pack adjacency to bits + init maxE ----------------
__global__ __launch_bounds__(256) void k_pack(const int* __restrict__ adj) {
    const int nwarps = (gridDim.x * blockDim.x) >> 5;
    const int wid    = (blockIdx.x * blockDim.x + threadIdx.x) >> 5;
    const int lane   = threadIdx.x & 31;
    const int total  = BB*NN*NW;
    for (int w = wid; w < total; w += nwarps) {
        int v = adj[(size_t)w * 32 + lane];
        unsigned m = __ballot_sync(0xffffffffu, v != 0);
        if (lane == 0) g_adj[w] = m;
    }
    if (blockIdx.x == 0 && threadIdx.x < BB*HH) g_maxE[threadIdx.x] = 0u;
}

// ---------------- kernel 2: Wh = x @ W  (8192x256x256 GEMM) ----------------
__global__ __launch_bounds__(256) void k_gemm1(const float* __restrict__ x,
                                               const float* __restrict__ W) {
    __shared__ float sX[16][68];   // [k][row], padded
    __shared__ float sW[16][64];   // [k][col]
    const int t  = threadIdx.x;
    const int rb = blockIdx.y * 64;           // row tile base (of 8192)
    const int cb = blockIdx.x * 64;           // col tile base (of 256)
    const int tr = (t >> 4) * 4;              // thread row offset (0..60)
    const int tc = (t & 15) * 4;              // thread col offset (0..60)
    unsigned long long acc[4][2];
#pragma unroll
    for (int i = 0; i < 4; i++) { acc[i][0] = 0ull; acc[i][1] = 0ull; }

    for (int kc = 0; kc < FIN; kc += 16) {
        {   // stage x tile (transposed): 64 rows x 16 k
            int row = t >> 2, k4 = (t & 3) * 4;
            float4 v = *(const float4*)(x + (size_t)(rb + row) * FIN + kc + k4);
            sX[k4+0][row] = v.x; sX[k4+1][row] = v.y;
            sX[k4+2][row] = v.z; sX[k4+3][row] = v.w;
        }
        {   // stage W tile: Wcat[f][h*32+d] = W[h][f][d]
            int c = t & 63, k0 = t >> 6;
            int col = cb + c;
            const float* wp = W + (size_t)(col >> 5) * (FIN*DD) + (col & 31);
#pragma unroll
            for (int i = 0; i < 4; i++) {
                int k = k0 + i * 4;
                sW[k][c] = wp[(size_t)(kc + k) * DD];
            }
        }
        __syncthreads();
#pragma unroll
        for (int k = 0; k < 16; k++) {
            float4 a4 = *(float4*)&sX[k][tr];
            ulonglong2 b2 = *(ulonglong2*)&sW[k][tc];
            unsigned long long a0 = pk2(a4.x, a4.x), a1 = pk2(a4.y, a4.y);
            unsigned long long a2 = pk2(a4.z, a4.z), a3 = pk2(a4.w, a4.w);
            ffma2(acc[0][0], a0, b2.x); ffma2(acc[0][1], a0, b2.y);
            ffma2(acc[1][0], a1, b2.x); ffma2(acc[1][1], a1, b2.y);
            ffma2(acc[2][0], a2, b2.x); ffma2(acc[2][1], a2, b2.y);
            ffma2(acc[3][0], a3, b2.x); ffma2(acc[3][1], a3, b2.y);
        }
        __syncthreads();
    }
#pragma unroll
    for (int i = 0; i < 4; i++) {
        int gr = rb + tr + i;
        int b  = gr >> 11, n = gr & (NN - 1);
#pragma unroll
        for (int j2 = 0; j2 < 2; j2++) {
            float2 v = upk2(acc[i][j2]);
            int col = cb + tc + j2 * 2;
            float* o = g_Wh + ((size_t)(b*HH + (col >> 5)) * NN + n) * DD + (col & 31);
            o[0] = v.x; o[1] = v.y;
        }
    }
}

// ---------------- kernel 3: e_src/e_dst + per-(b,h) max of e_dst ----------------
__global__ __launch_bounds__(256) void k_e(const float* __restrict__ a) {
    int idx = blockIdx.x * blockDim.x + threadIdx.x;     // < B*H*N
    int bh  = idx >> 11;
    int h   = bh & (HH - 1);
    const float* wh = g_Wh + (size_t)idx * DD;
    float es = 0.f, ed = 0.f;
#pragma unroll
    for (int d4 = 0; d4 < 8; d4++) {
        float4 w  = *(const float4*)(wh + d4 * 4);
        float4 as = *(const float4*)(a + h * 64 + d4 * 4);
        float4 ad = *(const float4*)(a + h * 64 + 32 + d4 * 4);
        es += w.x*as.x + w.y*as.y + w.z*as.z + w.w*as.w;
        ed += w.x*ad.x + w.y*ad.y + w.z*ad.z + w.w*ad.w;
    }
    g_esrc[idx] = es;
    g_edst[idx] = ed;
    // orderable-uint mapping for float max
    unsigned u = __float_as_uint(ed);
    u = (u & 0x80000000u) ? ~u : (u | 0x80000000u);
#pragma unroll
    for (int o = 16; o; o >>= 1) {
        unsigned v = __shfl_xor_sync(0xffffffffu, u, o);
        u = (v > u) ? v : u;
    }
    if ((threadIdx.x & 31) == 0) atomicMax(&g_maxE[bh], u);
}

// ---------------- kernel 4: factorized exponentials ----------------
__global__ __launch_bounds__(256) void k_exp() {
    int idx = blockIdx.x * blockDim.x + threadIdx.x;
    int bh  = idx >> 11;
    unsigned u = g_maxE[bh];
    float maxE = (u & 0x80000000u) ? __uint_as_float(u ^ 0x80000000u)
                                   : __uint_as_float(~u);
    float es = g_esrc[idx], ed = g_edst[idx];
    float m  = es + maxE;
    m = fmaxf(m, 0.2f * m);                 // leaky-relu upper bound for this row
    g_AI[idx] = make_float4(-es, __expf(es - m), __expf(0.2f * es - m), 0.f);
    g_EJ[idx] = make_float4(ed, __expf(ed), __expf(0.2f * ed), 0.f);
}

// ---------------- kernel 5: attention mainloop ----------------
// Block: (b, 64-row i-tile), all 8 heads. Thread: 4 rows x 16 d-cols of one head.
__global__ __launch_bounds__(256) void k_attn(float* __restrict__ out) {
    __shared__ float4   sWh[32 * 64];   // [jj][plane(h*8+d4)] XOR-swizzled, 32KB
    __shared__ float4   sEJ[8][33];     // padded against bank conflicts
    __shared__ unsigned sAdj[64];
    const int t  = threadIdx.x;
    const int b  = blockIdx.y;
    const int i0 = blockIdx.x * 64;
    const int dg = t & 1;               // d-half: 0 or 1 (16 cols each)
    const int h  = (t >> 1) & 7;
    const int rg = t >> 4;              // 0..15 row groups of 4
    const int bh = b * HH + h;

    float thr[4], A1c[4], A2c[4], sum[4];
#pragma unroll
    for (int r = 0; r < 4; r++) {
        float4 ai = g_AI[(size_t)bh * NN + i0 + rg * 4 + r];
        thr[r] = ai.x; A1c[r] = ai.y; A2c[r] = ai.z; sum[r] = 0.f;
    }
    unsigned long long acc[4][8];
#pragma unroll
    for (int r = 0; r < 4; r++)
#pragma unroll
        for (int k = 0; k < 8; k++) acc[r][k] = 0ull;

    for (int jb = 0; jb < NW; jb++) {
        int j0 = jb * 32;
#pragma unroll
        for (int it = 0; it < 8; it++) {   // stage Wh tile [8h][32j][32d]
            int q   = t + it * 256;
            int jj  = q >> 6;
            int pl  = q & 63;
            int pls = pl ^ ((pl >> 3) & 7);
            sWh[jj * 64 + pls] = *(const float4*)(
                g_Wh + ((size_t)(b*HH + (pl >> 3)) * NN + j0 + jj) * DD + (pl & 7) * 4);
        }
        {   // stage EJ
            int h2 = t >> 5, jj = t & 31;
            sEJ[h2][jj] = g_EJ[(size_t)(b*HH + h2) * NN + j0 + jj];
        }
        if (t < 64) sAdj[t] = g_adj[((size_t)b * NN + i0 + t) * NW + jb];
        __syncthreads();

        unsigned aw[4];
#pragma unroll
        for (int r = 0; r < 4; r++) aw[r] = sAdj[rg * 4 + r];

#pragma unroll 8
        for (int jj = 0; jj < 32; jj++) {
            float4 ev = sEJ[h][jj];                       // (e_dst, E1, E2)
            unsigned long long wp[8];
#pragma unroll
            for (int k = 0; k < 4; k++) {
                int pl  = h * 8 + dg * 4 + k;
                int pls = pl ^ ((pl >> 3) & 7);
                ulonglong2 w2 = *(ulonglong2*)&sWh[jj * 64 + pls];
                wp[k*2] = w2.x; wp[k*2+1] = w2.y;
            }
#pragma unroll
            for (int r = 0; r < 4; r++) {
                bool pos = (ev.x > thr[r]);               // s>0  <=>  e_dst > -e_src
                float ez = pos ? ev.y : ev.z;
                float am = pos ? A1c[r] : A2c[r];
                if (!((aw[r] >> jj) & 1u)) ez = 0.f;
                float p = am * ez;                        // = exp(LR(s) - m_i), in [0,1]
                sum[r] += p;
                unsigned long long pp = pk2(p, p);
#pragma unroll
                for (int k = 0; k < 8; k++) ffma2(acc[r][k], pp, wp[k]);
            }
        }
        __syncthreads();
    }
#pragma unroll
    for (int r = 0; r < 4; r++) {
        float inv = 1.0f / sum[r];
        int i = i0 + rg * 4 + r;
        float4* op = (float4*)(out + ((size_t)b * NN + i) * (HH*DD) + h * DD + dg * 16);
#pragma unroll
        for (int k = 0; k < 4; k++) {
            float2 v0 = upk2(acc[r][2*k]);
            float2 v1 = upk2(acc[r][2*k+1]);
            op[k] = make_float4(v0.x * inv, v0.y * inv, v1.x * inv, v1.y * inv);
        }
    }
}

// ---------------- launch ----------------
extern "C" void kernel_launch(void* const* d_in, const int* in_sizes, int n_in,
                              void* d_out, int out_size) {
    const float* x   = (const float*)d_in[0];
    const int*   adj = (const int*)  d_in[1];
    const float* W   = (const float*)d_in[2];
    const float* a   = (const float*)d_in[3];
    float* out = (float*)d_out;

    k_pack <<<2048, 256>>>(adj);
    k_gemm1<<<dim3(4, 128), 256>>>(x, W);
    k_e    <<<(BB*HH*NN)/256, 256>>>(a);
    k_exp  <<<(BB*HH*NN)/256, 256>>>();
    k_attn <<<dim3(NN/64, BB), 256>>>(out);
}

// round 5
// speedup vs baseline: 2.0600x; 2.0600x over previous
#include <cuda_runtime.h>
#include <cuda_bf16.h>
#include <cstdint>

#define BB  4
#define NN  2048
#define FIN 256
#define HH  8
#define DD  32
#define NW  (NN/32)   // 64 adj words per row

// ---------------- device scratch (no allocations allowed) ----------------
__device__ float    g_Wh[BB*HH*NN*DD];     // [b][h][n][d]  8.4MB
__device__ float    g_esrc[BB*HH*NN];
__device__ float    g_edst[BB*HH*NN];
__device__ float4   g_AI[BB*HH*NN];        // (-e_src, A1, A2, 0)
__device__ float4   g_EJ[BB*HH*NN];        // (e_dst,  E1, E2, 0)
__device__ unsigned g_maxE[BB*HH];
__device__ unsigned g_adj[BB*NN*NW];       // packed adjacency bits, TRANSPOSED [b][jw][i]

// ---------------- f32x2 packed-FMA helpers (sm_103a, portable PTX) ----------------
__device__ __forceinline__ void ffma2(unsigned long long &acc,
                                      unsigned long long a, unsigned long long b) {
    asm("fma.rn.f32x2 %0, %1, %2, %0;" : "+l"(acc) : "l"(a), "l"(b));
}
__device__ __forceinline__ unsigned long long pk2(float lo, float hi) {
    unsigned long long r;
    asm("mov.b64 %0, {%1, %2};" : "=l"(r) : "f"(lo), "f"(hi));
    return r;
}
__device__ __forceinline__ float2 upk2(unsigned long long v) {
    float2 r;
    asm("mov.b64 {%0, %1}, %2;" : "=f"(r.x), "=f"(r.y) : "l"(v));
    return r;
}

// ---------------- tf32 mma.sync helpers (sm_80+ portable PTX) ----------------
__device__ __forceinline__ uint32_t f2tf(float f) {
    uint32_t r;
    asm("cvt.rna.tf32.f32 %0, %1;" : "=r"(r) : "f"(f));
    return r;
}
__device__ __forceinline__ void mma_tf32(float* c,
                                         uint32_t a0, uint32_t a1, uint32_t a2, uint32_t a3,
                                         uint32_t b0, uint32_t b1) {
    asm volatile(
        "mma.sync.aligned.m16n8k8.row.col.f32.tf32.tf32.f32 "
        "{%0,%1,%2,%3}, {%4,%5,%6,%7}, {%8,%9}, {%0,%1,%2,%3};"
        : "+f"(c[0]), "+f"(c[1]), "+f"(c[2]), "+f"(c[3])
        : "r"(a0), "r"(a1), "r"(a2), "r"(a3), "r"(b0), "r"(b1));
}

// ---------------- kernel 1: pack adjacency to bits (transposed) + init maxE ----------------
__global__ __launch_bounds__(256) void k_pack(const int* __restrict__ adj) {
    const int nwarps = (gridDim.x * blockDim.x) >> 5;
    const int wid    = (blockIdx.x * blockDim.x + threadIdx.x) >> 5;
    const int lane   = threadIdx.x & 31;
    const int total  = BB*NN*NW;
    for (int w = wid; w < total; w += nwarps) {
        int v = adj[(size_t)w * 32 + lane];
        unsigned m = __ballot_sync(0xffffffffu, v != 0);
        if (lane == 0) {
            int b  = w / (NN*NW);
            int r  = w - b * (NN*NW);
            int i  = r / NW;
            int jw = r - i * NW;
            g_adj[((size_t)b * NW + jw) * NN + i] = m;   // transposed for coalesced attn reads
        }
    }
    if (blockIdx.x == 0 && threadIdx.x < BB*HH) g_maxE[threadIdx.x] = 0u;
}

// ---------------- kernel 2: Wh = x @ W  (8192x256x256 GEMM, fp32 exact) ----------------
__global__ __launch_bounds__(256) void k_gemm1(const float* __restrict__ x,
                                               const float* __restrict__ W) {
    __shared__ float sX[16][68];
    __shared__ float sW[16][64];
    const int t  = threadIdx.x;
    const int rb = blockIdx.y * 64;
    const int cb = blockIdx.x * 64;
    const int tr = (t >> 4) * 4;
    const int tc = (t & 15) * 4;
    unsigned long long acc[4][2];
#pragma unroll
    for (int i = 0; i < 4; i++) { acc[i][0] = 0ull; acc[i][1] = 0ull; }

    for (int kc = 0; kc < FIN; kc += 16) {
        {
            int row = t >> 2, k4 = (t & 3) * 4;
            float4 v = *(const float4*)(x + (size_t)(rb + row) * FIN + kc + k4);
            sX[k4+0][row] = v.x; sX[k4+1][row] = v.y;
            sX[k4+2][row] = v.z; sX[k4+3][row] = v.w;
        }
        {
            int c = t & 63, k0 = t >> 6;
            int col = cb + c;
            const float* wp = W + (size_t)(col >> 5) * (FIN*DD) + (col & 31);
#pragma unroll
            for (int i = 0; i < 4; i++) {
                int k = k0 + i * 4;
                sW[k][c] = wp[(size_t)(kc + k) * DD];
            }
        }
        __syncthreads();
#pragma unroll
        for (int k = 0; k < 16; k++) {
            float4 a4 = *(float4*)&sX[k][tr];
            ulonglong2 b2 = *(ulonglong2*)&sW[k][tc];
            unsigned long long a0 = pk2(a4.x, a4.x), a1 = pk2(a4.y, a4.y);
            unsigned long long a2 = pk2(a4.z, a4.z), a3 = pk2(a4.w, a4.w);
            ffma2(acc[0][0], a0, b2.x); ffma2(acc[0][1], a0, b2.y);
            ffma2(acc[1][0], a1, b2.x); ffma2(acc[1][1], a1, b2.y);
            ffma2(acc[2][0], a2, b2.x); ffma2(acc[2][1], a2, b2.y);
            ffma2(acc[3][0], a3, b2.x); ffma2(acc[3][1], a3, b2.y);
        }
        __syncthreads();
    }
#pragma unroll
    for (int i = 0; i < 4; i++) {
        int gr = rb + tr + i;
        int b  = gr >> 11, n = gr & (NN - 1);
#pragma unroll
        for (int j2 = 0; j2 < 2; j2++) {
            float2 v = upk2(acc[i][j2]);
            int col = cb + tc + j2 * 2;
            float* o = g_Wh + ((size_t)(b*HH + (col >> 5)) * NN + n) * DD + (col & 31);
            o[0] = v.x; o[1] = v.y;
        }
    }
}

// ---------------- kernel 3: e_src/e_dst + per-(b,h) max of e_dst ----------------
__global__ __launch_bounds__(256) void k_e(const float* __restrict__ a) {
    int idx = blockIdx.x * blockDim.x + threadIdx.x;
    int bh  = idx >> 11;
    int h   = bh & (HH - 1);
    const float* wh = g_Wh + (size_t)idx * DD;
    float es = 0.f, ed = 0.f;
#pragma unroll
    for (int d4 = 0; d4 < 8; d4++) {
        float4 w  = *(const float4*)(wh + d4 * 4);
        float4 as = *(const float4*)(a + h * 64 + d4 * 4);
        float4 ad = *(const float4*)(a + h * 64 + 32 + d4 * 4);
        es += w.x*as.x + w.y*as.y + w.z*as.z + w.w*as.w;
        ed += w.x*ad.x + w.y*ad.y + w.z*ad.z + w.w*ad.w;
    }
    g_esrc[idx] = es;
    g_edst[idx] = ed;
    unsigned u = __float_as_uint(ed);
    u = (u & 0x80000000u) ? ~u : (u | 0x80000000u);
#pragma unroll
    for (int o = 16; o; o >>= 1) {
        unsigned v = __shfl_xor_sync(0xffffffffu, u, o);
        u = (v > u) ? v : u;
    }
    if ((threadIdx.x & 31) == 0) atomicMax(&g_maxE[bh], u);
}

// ---------------- kernel 4: factorized exponentials ----------------
__global__ __launch_bounds__(256) void k_exp() {
    int idx = blockIdx.x * blockDim.x + threadIdx.x;
    int bh  = idx >> 11;
    unsigned u = g_maxE[bh];
    float maxE = (u & 0x80000000u) ? __uint_as_float(u ^ 0x80000000u)
                                   : __uint_as_float(~u);
    float es = g_esrc[idx], ed = g_edst[idx];
    float m  = es + maxE;
    m = fmaxf(m, 0.2f * m);
    g_AI[idx] = make_float4(-es, __expf(es - m), __expf(0.2f * es - m), 0.f);
    g_EJ[idx] = make_float4(ed, __expf(ed), __expf(0.2f * ed), 0.f);
}

// ---------------- kernel 5: attention via mma.sync tf32 ----------------
// CTA = (b, h, 128-row i-tile), 256 threads (8 warps x 16 rows).
// Per 32-j chunk: each thread builds its 4 A-fragment p-values in registers
// (softmax factorization), Wh chunk staged in SMEM pre-converted to tf32 in
// B-fragment order (conflict-free LDS.64), 16 mma.sync per warp per chunk.
__global__ __launch_bounds__(256) void k_attn(float* __restrict__ out) {
    __shared__ uint32_t sB[2][1024];      // 2 x 4KB, tf32 bits in fragment order
    __shared__ float4   sEJ[2][32];
    const int t    = threadIdx.x;
    const int lane = t & 31;
    const int wid  = t >> 5;
    const int g    = lane >> 2;
    const int tig  = lane & 3;
    const int bh   = blockIdx.y;
    const int b    = bh >> 3;
    const int h    = bh & 7;
    const int i0   = blockIdx.x * 128;
    const int r0   = i0 + wid * 16 + g;   // global row (i) for a0/a2/c0/c1
    const int r1   = r0 + 8;              // global row for a1/a3/c2/c3

    const float4 ai0 = g_AI[(size_t)bh * NN + r0];
    const float4 ai1 = g_AI[(size_t)bh * NN + r1];
    const float thr0 = ai0.x, A10 = ai0.y, A20 = ai0.z;
    const float thr1 = ai1.x, A11 = ai1.y, A21 = ai1.z;
    float rs0 = 0.f, rs1 = 0.f;
    float acc[16];
#pragma unroll
    for (int i = 0; i < 16; i++) acc[i] = 0.f;

    const float4*   whp4 = (const float4*)(g_Wh + (size_t)bh * NN * DD);
    const float4*   ejp4 = (const float4*)g_EJ + (size_t)bh * NN;
    const unsigned* adjp = g_adj + (size_t)b * NW * NN;

    // staging geometry for this thread (fixed): Wh row j = t>>3, cols (t&7)*4 ..+3
    const int sj    = t >> 3;
    const int sw    = sj >> 3;            // k8 window
    const int sk    = sj & 3;
    const int shalf = (sj >> 2) & 1;
    const int dbase = (t & 7) * 4;

    // ---- prologue: stage chunk 0 ----
    {
        float4 vB = whp4[(size_t)sj * 8 + (t & 7)];
        if (t < 32) sEJ[0][t] = ejp4[t];
#pragma unroll
        for (int u = 0; u < 4; u++) {
            int d = dbase + u;
            int idx = ((sw << 2) + (d >> 3)) * 64 + (((d & 7) << 2) + sk) * 2 + shalf;
            sB[0][idx] = f2tf((&vB.x)[u]);
        }
    }
    unsigned aw0 = adjp[r0], aw1 = adjp[r1];
    __syncthreads();

    for (int c = 0; c < 64; c++) {
        const int buf = c & 1;
        // ---- prefetch chunk c+1 (clamped; redundant on last iter) ----
        const int cn = (c + 1 < 64) ? c + 1 : 0;
        float4 vB = whp4[((size_t)cn * 32 + sj) * 8 + (t & 7)];
        float4 vE = make_float4(0.f, 0.f, 0.f, 0.f);
        if (t < 32) vE = ejp4[cn * 32 + t];
        unsigned awn0 = adjp[(size_t)cn * NN + r0];
        unsigned awn1 = adjp[(size_t)cn * NN + r1];

        // ---- inner: 4 k8 windows ----
        const float4*   EJ = sEJ[buf];
        const uint32_t* Bf = sB[buf];
#pragma unroll
        for (int w = 0; w < 4; w++) {
            float4 ev0 = EJ[w * 8 + tig];
            float4 ev1 = EJ[w * 8 + tig + 4];
            float p0 = (ev0.x > thr0) ? A10 * ev0.y : A20 * ev0.z;
            float p1 = (ev0.x > thr1) ? A11 * ev0.y : A21 * ev0.z;
            float p2 = (ev1.x > thr0) ? A10 * ev1.y : A20 * ev1.z;
            float p3 = (ev1.x > thr1) ? A11 * ev1.y : A21 * ev1.z;
            const int jb = w * 8 + tig;
            if (!((aw0 >> jb) & 1u))       p0 = 0.f;
            if (!((aw1 >> jb) & 1u))       p1 = 0.f;
            if (!((aw0 >> (jb + 4)) & 1u)) p2 = 0.f;
            if (!((aw1 >> (jb + 4)) & 1u)) p3 = 0.f;
            rs0 += p0 + p2;
            rs1 += p1 + p3;
            uint32_t a0 = f2tf(p0), a1 = f2tf(p1), a2 = f2tf(p2), a3 = f2tf(p3);
#pragma unroll
            for (int nb = 0; nb < 4; nb++) {
                uint2 bb = *(const uint2*)&Bf[((w << 2) + nb) * 64 + lane * 2];
                mma_tf32(acc + nb * 4, a0, a1, a2, a3, bb.x, bb.y);
            }
        }

        // ---- stage chunk c+1 into the other buffer ----
        const int nbuf = buf ^ 1;
        if (t < 32) sEJ[nbuf][t] = vE;
#pragma unroll
        for (int u = 0; u < 4; u++) {
            int d = dbase + u;
            int idx = ((sw << 2) + (d >> 3)) * 64 + (((d & 7) << 2) + sk) * 2 + shalf;
            sB[nbuf][idx] = f2tf((&vB.x)[u]);
        }
        aw0 = awn0; aw1 = awn1;
        __syncthreads();
    }

    // ---- epilogue: quad-reduce row sums, normalize, store ----
    rs0 += __shfl_xor_sync(0xffffffffu, rs0, 1);
    rs0 += __shfl_xor_sync(0xffffffffu, rs0, 2);
    rs1 += __shfl_xor_sync(0xffffffffu, rs1, 1);
    rs1 += __shfl_xor_sync(0xffffffffu, rs1, 2);
    const float inv0 = 1.0f / rs0;
    const float inv1 = 1.0f / rs1;

    float* o0 = out + ((size_t)(b * NN + r0)) * (HH * DD) + h * DD + tig * 2;
    float* o1 = out + ((size_t)(b * NN + r1)) * (HH * DD) + h * DD + tig * 2;
#pragma unroll
    for (int nb = 0; nb < 4; nb++) {
        *(float2*)(o0 + nb * 8) = make_float2(acc[nb*4 + 0] * inv0, acc[nb*4 + 1] * inv0);
        *(float2*)(o1 + nb * 8) = make_float2(acc[nb*4 + 2] * inv1, acc[nb*4 + 3] * inv1);
    }
}

// ---------------- launch ----------------
extern "C" void kernel_launch(void* const* d_in, const int* in_sizes, int n_in,
                              void* d_out, int out_size) {
    const float* x   = (const float*)d_in[0];
    const int*   adj = (const int*)  d_in[1];
    const float* W   = (const float*)d_in[2];
    const float* a   = (const float*)d_in[3];
    float* out = (float*)d_out;

    k_pack <<<2048, 256>>>(adj);
    k_gemm1<<<dim3(4, 128), 256>>>(x, W);
    k_e    <<<(BB*HH*NN)/256, 256>>>(a);
    k_exp  <<<(BB*HH*NN)/256, 256>>>();
    k_attn <<<dim3(NN/128, BB*HH), 256>>>(out);
}

// round 7
// speedup vs baseline: 2.1862x; 1.0613x over previous
#include <cuda_runtime.h>
#include <cuda_bf16.h>
#include <cstdint>

#define BB  4
#define NN  2048
#define FIN 256
#define HH  8
#define DD  32
#define NW  (NN/32)   // 64 adj words per row

// ---------------- device scratch (no allocations allowed) ----------------
__device__ float    g_Wh[BB*HH*NN*DD];     // [b][h][n][d]  8.4MB
__device__ float    g_esrc[BB*HH*NN];
__device__ float    g_edst[BB*HH*NN];
__device__ float4   g_AI[BB*HH*NN];        // (-e_src, A1, A2, 0)
__device__ float4   g_EJ[BB*HH*NN];        // (e_dst,  E1, E2, 0)
__device__ unsigned g_maxE[BB*HH];
__device__ unsigned g_adj[BB*NN*NW];       // packed adjacency bits, TRANSPOSED [b][jw][i]

// ---------------- tf32 mma.sync helpers (sm_80+ portable PTX) ----------------
__device__ __forceinline__ uint32_t f2tf(float f) {
    uint32_t r;
    asm("cvt.rna.tf32.f32 %0, %1;" : "=r"(r) : "f"(f));
    return r;
}
__device__ __forceinline__ void split_tf32(float v, uint32_t &hi, uint32_t &lo) {
    hi = f2tf(v);
    lo = f2tf(v - __uint_as_float(hi));
}
__device__ __forceinline__ void mma_tf32(float* c,
                                         uint32_t a0, uint32_t a1, uint32_t a2, uint32_t a3,
                                         uint32_t b0, uint32_t b1) {
    asm volatile(
        "mma.sync.aligned.m16n8k8.row.col.f32.tf32.tf32.f32 "
        "{%0,%1,%2,%3}, {%4,%5,%6,%7}, {%8,%9}, {%0,%1,%2,%3};"
        : "+f"(c[0]), "+f"(c[1]), "+f"(c[2]), "+f"(c[3])
        : "r"(a0), "r"(a1), "r"(a2), "r"(a3), "r"(b0), "r"(b1));
}

// ---------------- kernel 1: pack adjacency to bits (transposed) + init maxE ----------------
__global__ __launch_bounds__(256) void k_pack(const int* __restrict__ adj) {
    const int nwarps = (gridDim.x * blockDim.x) >> 5;
    const int wid    = (blockIdx.x * blockDim.x + threadIdx.x) >> 5;
    const int lane   = threadIdx.x & 31;
    const int total  = BB*NN*NW;
    for (int w = wid; w < total; w += nwarps) {
        int v = adj[(size_t)w * 32 + lane];
        unsigned m = __ballot_sync(0xffffffffu, v != 0);
        if (lane == 0) {
            int b  = w / (NN*NW);
            int r  = w - b * (NN*NW);
            int i  = r / NW;
            int jw = r - i * NW;
            g_adj[((size_t)b * NW + jw) * NN + i] = m;
        }
    }
    if (blockIdx.x == 0 && threadIdx.x < BB*HH) g_maxE[threadIdx.x] = 0u;
}

// ---------------- kernel 2: Wh = x @ W via 3xTF32 mma.sync (fp32-accurate) ----------------
// CTA: 128 rows x 128 cols, 256 threads (8 warps: 4 along M x 2 along N).
// K in 16-wide chunks; A/B split into tf32 hi+lo; Wh = Ah*Bh + Al*Bh + Ah*Bl.
// SMEM padded layouts chosen for conflict-free fragment LDS.
__global__ __launch_bounds__(256) void k_gemm1(const float* __restrict__ x,
                                               const float* __restrict__ W) {
    __shared__ uint32_t sAh[128*20], sAl[128*20];    // [row][k16 pad 20]
    __shared__ uint32_t sBh[16*136], sBl[16*136];    // [k16][col128 pad 136]
    const int t    = threadIdx.x;
    const int lane = t & 31;
    const int wid  = t >> 5;
    const int g    = lane >> 2;
    const int tig  = lane & 3;
    const int wy   = wid & 3;            // M: 4 warps x 32 rows
    const int wx   = wid >> 2;           // N: 2 warps x 64 cols
    const int rb   = blockIdx.y * 128;   // global row base
    const int cb   = blockIdx.x * 128;   // global col base

    // staging descriptors
    const int row_a = t >> 1;            // A: thread loads row row_a, k8 half (t&1)
    const int kb_a  = (t & 1) * 8;
    const int col_b = t & 127;           // B: thread loads col col_b, k8 half (t>>7)
    const int kb_b  = (t >> 7) * 8;
    const int col_g = cb + col_b;
    const float* wp = W + (size_t)(col_g >> 5) * (FIN*DD) + (col_g & 31);
    const float* xp = x + (size_t)(rb + row_a) * FIN + kb_a;

    float acc[2][8][4];
#pragma unroll
    for (int mi = 0; mi < 2; mi++)
#pragma unroll
        for (int nb = 0; nb < 8; nb++)
#pragma unroll
            for (int q = 0; q < 4; q++) acc[mi][nb][q] = 0.f;

    // prologue: load chunk 0 into registers
    float4 va0 = *(const float4*)(xp);
    float4 va1 = *(const float4*)(xp + 4);
    float  vb[8];
#pragma unroll
    for (int i = 0; i < 8; i++) vb[i] = wp[(size_t)(kb_b + i) * DD];

    for (int ch = 0; ch < 16; ch++) {
        __syncthreads();
        // ---- store staged chunk (split to tf32 hi/lo) ----
        {
            float av[8] = {va0.x, va0.y, va0.z, va0.w, va1.x, va1.y, va1.z, va1.w};
#pragma unroll
            for (int i = 0; i < 8; i++) {
                uint32_t hi, lo;
                split_tf32(av[i], hi, lo);
                sAh[row_a * 20 + kb_a + i] = hi;
                sAl[row_a * 20 + kb_a + i] = lo;
            }
#pragma unroll
            for (int i = 0; i < 8; i++) {
                uint32_t hi, lo;
                split_tf32(vb[i], hi, lo);
                sBh[(kb_b + i) * 136 + col_b] = hi;
                sBl[(kb_b + i) * 136 + col_b] = lo;
            }
        }
        __syncthreads();
        // ---- prefetch next chunk ----
        if (ch < 15) {
            const int kc = (ch + 1) * 16;
            va0 = *(const float4*)(xp + kc);
            va1 = *(const float4*)(xp + kc + 4);
#pragma unroll
            for (int i = 0; i < 8; i++) vb[i] = wp[(size_t)(kc + kb_b + i) * DD];
        }
        // ---- compute: 2 k8 windows ----
#pragma unroll
        for (int w = 0; w < 2; w++) {
            uint32_t ah[2][4], al[2][4];
#pragma unroll
            for (int mi = 0; mi < 2; mi++) {
                int base = (wy*32 + mi*16 + g) * 20 + w*8 + tig;
                ah[mi][0] = sAh[base];       ah[mi][1] = sAh[base + 160];
                ah[mi][2] = sAh[base + 4];   ah[mi][3] = sAh[base + 164];
                al[mi][0] = sAl[base];       al[mi][1] = sAl[base + 160];
                al[mi][2] = sAl[base + 4];   al[mi][3] = sAl[base + 164];
            }
#pragma unroll
            for (int nb = 0; nb < 8; nb++) {
                int bbase = (w*8 + tig) * 136 + wx*64 + nb*8 + g;
                uint32_t bh0 = sBh[bbase], bh1 = sBh[bbase + 4*136];
                uint32_t bl0 = sBl[bbase], bl1 = sBl[bbase + 4*136];
#pragma unroll
                for (int mi = 0; mi < 2; mi++) {
                    float* c = acc[mi][nb];
                    mma_tf32(c, ah[mi][0], ah[mi][1], ah[mi][2], ah[mi][3], bh0, bh1);
                    mma_tf32(c, al[mi][0], al[mi][1], al[mi][2], al[mi][3], bh0, bh1);
                    mma_tf32(c, ah[mi][0], ah[mi][1], ah[mi][2], ah[mi][3], bl0, bl1);
                }
            }
        }
    }

    // ---- epilogue: write Wh[b][h][n][d] ----
#pragma unroll
    for (int mi = 0; mi < 2; mi++) {
        int r0 = rb + wy*32 + mi*16 + g;
        int r1 = r0 + 8;
        int b0 = r0 >> 11, n0 = r0 & (NN-1);
        int b1 = r1 >> 11, n1 = r1 & (NN-1);
#pragma unroll
        for (int nb = 0; nb < 8; nb++) {
            int col = cb + wx*64 + nb*8 + tig*2;
            int h = col >> 5, d = col & 31;
            float* o0 = g_Wh + ((size_t)(b0*HH + h) * NN + n0) * DD + d;
            float* o1 = g_Wh + ((size_t)(b1*HH + h) * NN + n1) * DD + d;
            *(float2*)o0 = make_float2(acc[mi][nb][0], acc[mi][nb][1]);
            *(float2*)o1 = make_float2(acc[mi][nb][2], acc[mi][nb][3]);
        }
    }
}

// ---------------- kernel 3: e_src/e_dst + per-(b,h) max of e_dst ----------------
__global__ __launch_bounds__(256) void k_e(const float* __restrict__ a) {
    int idx = blockIdx.x * blockDim.x + threadIdx.x;
    int bh  = idx >> 11;
    int h   = bh & (HH - 1);
    const float* wh = g_Wh + (size_t)idx * DD;
    float es = 0.f, ed = 0.f;
#pragma unroll
    for (int d4 = 0; d4 < 8; d4++) {
        float4 w  = *(const float4*)(wh + d4 * 4);
        float4 as = *(const float4*)(a + h * 64 + d4 * 4);
        float4 ad = *(const float4*)(a + h * 64 + 32 + d4 * 4);
        es += w.x*as.x + w.y*as.y + w.z*as.z + w.w*as.w;
        ed += w.x*ad.x + w.y*ad.y + w.z*ad.z + w.w*ad.w;
    }
    g_esrc[idx] = es;
    g_edst[idx] = ed;
    unsigned u = __float_as_uint(ed);
    u = (u & 0x80000000u) ? ~u : (u | 0x80000000u);
#pragma unroll
    for (int o = 16; o; o >>= 1) {
        unsigned v = __shfl_xor_sync(0xffffffffu, u, o);
        u = (v > u) ? v : u;
    }
    if ((threadIdx.x & 31) == 0) atomicMax(&g_maxE[bh], u);
}

// ---------------- kernel 4: factorized exponentials ----------------
__global__ __launch_bounds__(256) void k_exp() {
    int idx = blockIdx.x * blockDim.x + threadIdx.x;
    int bh  = idx >> 11;
    unsigned u = g_maxE[bh];
    float maxE = (u & 0x80000000u) ? __uint_as_float(u ^ 0x80000000u)
                                   : __uint_as_float(~u);
    float es = g_esrc[idx], ed = g_edst[idx];
    float m  = es + maxE;
    m = fmaxf(m, 0.2f * m);
    g_AI[idx] = make_float4(-es, __expf(es - m), __expf(0.2f * es - m), 0.f);
    g_EJ[idx] = make_float4(ed, __expf(ed), __expf(0.2f * ed), 0.f);
}

// ---------------- kernel 5: attention via mma.sync tf32 ----------------
__global__ __launch_bounds__(256) void k_attn(float* __restrict__ out) {
    __shared__ uint32_t sB[2][1024];      // 2 x 4KB, tf32 bits in fragment order
    __shared__ float4   sEJ[2][32];
    const int t    = threadIdx.x;
    const int lane = t & 31;
    const int wid  = t >> 5;
    const int g    = lane >> 2;
    const int tig  = lane & 3;
    const int bh   = blockIdx.y;
    const int b    = bh >> 3;
    const int h    = bh & 7;
    const int i0   = blockIdx.x * 128;
    const int r0   = i0 + wid * 16 + g;
    const int r1   = r0 + 8;

    const float4 ai0 = g_AI[(size_t)bh * NN + r0];
    const float4 ai1 = g_AI[(size_t)bh * NN + r1];
    const float thr0 = ai0.x, A10 = ai0.y, A20 = ai0.z;
    const float thr1 = ai1.x, A11 = ai1.y, A21 = ai1.z;
    float rs0 = 0.f, rs1 = 0.f;
    float acc[16];
#pragma unroll
    for (int i = 0; i < 16; i++) acc[i] = 0.f;

    const float4*   whp4 = (const float4*)(g_Wh + (size_t)bh * NN * DD);
    const float4*   ejp4 = (const float4*)g_EJ + (size_t)bh * NN;
    const unsigned* adjp = g_adj + (size_t)b * NW * NN;

    const int sj    = t >> 3;
    const int sw    = sj >> 3;
    const int sk    = sj & 3;
    const int shalf = (sj >> 2) & 1;
    const int dbase = (t & 7) * 4;

    {
        float4 vB = whp4[(size_t)sj * 8 + (t & 7)];
        if (t < 32) sEJ[0][t] = ejp4[t];
#pragma unroll
        for (int u = 0; u < 4; u++) {
            int d = dbase + u;
            int idx = ((sw << 2) + (d >> 3)) * 64 + (((d & 7) << 2) + sk) * 2 + shalf;
            sB[0][idx] = f2tf((&vB.x)[u]);
        }
    }
    unsigned aw0 = adjp[r0], aw1 = adjp[r1];
    __syncthreads();

    for (int c = 0; c < 64; c++) {
        const int buf = c & 1;
        const int cn = (c + 1 < 64) ? c + 1 : 0;
        float4 vB = whp4[((size_t)cn * 32 + sj) * 8 + (t & 7)];
        float4 vE = make_float4(0.f, 0.f, 0.f, 0.f);
        if (t < 32) vE = ejp4[cn * 32 + t];
        unsigned awn0 = adjp[(size_t)cn * NN + r0];
        unsigned awn1 = adjp[(size_t)cn * NN + r1];

        const float4*   EJ = sEJ[buf];
        const uint32_t* Bf = sB[buf];
#pragma unroll
        for (int w = 0; w < 4; w++) {
            float4 ev0 = EJ[w * 8 + tig];
            float4 ev1 = EJ[w * 8 + tig + 4];
            float p0 = (ev0.x > thr0) ? A10 * ev0.y : A20 * ev0.z;
            float p1 = (ev0.x > thr1) ? A11 * ev0.y : A21 * ev0.z;
            float p2 = (ev1.x > thr0) ? A10 * ev1.y : A20 * ev1.z;
            float p3 = (ev1.x > thr1) ? A11 * ev1.y : A21 * ev1.z;
            const int jb = w * 8 + tig;
            if (!((aw0 >> jb) & 1u))       p0 = 0.f;
            if (!((aw1 >> jb) & 1u))       p1 = 0.f;
            if (!((aw0 >> (jb + 4)) & 1u)) p2 = 0.f;
            if (!((aw1 >> (jb + 4)) & 1u)) p3 = 0.f;
            rs0 += p0 + p2;
            rs1 += p1 + p3;
            uint32_t a0 = f2tf(p0), a1 = f2tf(p1), a2 = f2tf(p2), a3 = f2tf(p3);
#pragma unroll
            for (int nb = 0; nb < 4; nb++) {
                uint2 bb = *(const uint2*)&Bf[((w << 2) + nb) * 64 + lane * 2];
                mma_tf32(acc + nb * 4, a0, a1, a2, a3, bb.x, bb.y);
            }
        }

        const int nbuf = buf ^ 1;
        if (t < 32) sEJ[nbuf][t] = vE;
#pragma unroll
        for (int u = 0; u < 4; u++) {
            int d = dbase + u;
            int idx = ((sw << 2) + (d >> 3)) * 64 + (((d & 7) << 2) + sk) * 2 + shalf;
            sB[nbuf][idx] = f2tf((&vB.x)[u]);
        }
        aw0 = awn0; aw1 = awn1;
        __syncthreads();
    }

    rs0 += __shfl_xor_sync(0xffffffffu, rs0, 1);
    rs0 += __shfl_xor_sync(0xffffffffu, rs0, 2);
    rs1 += __shfl_xor_sync(0xffffffffu, rs1, 1);
    rs1 += __shfl_xor_sync(0xffffffffu, rs1, 2);
    const float inv0 = 1.0f / rs0;
    const float inv1 = 1.0f / rs1;

    float* o0 = out + ((size_t)(b * NN + r0)) * (HH * DD) + h * DD + tig * 2;
    float* o1 = out + ((size_t)(b * NN + r1)) * (HH * DD) + h * DD + tig * 2;
#pragma unroll
    for (int nb = 0; nb < 4; nb++) {
        *(float2*)(o0 + nb * 8) = make_float2(acc[nb*4 + 0] * inv0, acc[nb*4 + 1] * inv0);
        *(float2*)(o1 + nb * 8) = make_float2(acc[nb*4 + 2] * inv1, acc[nb*4 + 3] * inv1);
    }
}

// ---------------- launch ----------------
extern "C" void kernel_launch(void* const* d_in, const int* in_sizes, int n_in,
                              void* d_out, int out_size) {
    const float* x   = (const float*)d_in[0];
    const int*   adj = (const int*)  d_in[1];
    const float* W   = (const float*)d_in[2];
    const float* a   = (const float*)d_in[3];
    float* out = (float*)d_out;

    k_pack <<<2048, 256>>>(adj);
    k_gemm1<<<dim3(2, 64), 256>>>(x, W);
    k_e    <<<(BB*HH*NN)/256, 256>>>(a);
    k_exp  <<<(BB*HH*NN)/256, 256>>>();
    k_attn <<<dim3(NN/128, BB*HH), 256>>>(out);
}

// round 9
// speedup vs baseline: 2.2831x; 1.0443x over previous
#include <cuda_runtime.h>
#include <cuda_bf16.h>
#include <cstdint>

#define BB  4
#define NN  2048
#define FIN 256
#define HH  8
#define DD  32
#define NW  (NN/32)   // 64 adj words per row

// ---------------- device scratch (no allocations allowed) ----------------
__device__ float    g_Wh[BB*HH*NN*DD];     // [b][h][n][d]  8.4MB
__device__ float    g_esrc[BB*HH*NN];
__device__ float    g_edst[BB*HH*NN];
__device__ float4   g_AI[BB*HH*NN];        // (-e_src, A1, A2, 0)
__device__ float4   g_EJ[BB*HH*NN];        // (e_dst,  E1, E2, 0)
__device__ unsigned g_maxE[BB*HH];
__device__ unsigned g_adj[BB*NN*NW];       // packed adjacency bits, TRANSPOSED [b][jw][i]

// ---------------- mma.sync helpers (sm_80+ portable PTX) ----------------
__device__ __forceinline__ uint32_t f2tf(float f) {
    uint32_t r;
    asm("cvt.rna.tf32.f32 %0, %1;" : "=r"(r) : "f"(f));
    return r;
}
__device__ __forceinline__ void mma_tf32(float* c,
                                         uint32_t a0, uint32_t a1, uint32_t a2, uint32_t a3,
                                         uint32_t b0, uint32_t b1) {
    asm volatile(
        "mma.sync.aligned.m16n8k8.row.col.f32.tf32.tf32.f32 "
        "{%0,%1,%2,%3}, {%4,%5,%6,%7}, {%8,%9}, {%0,%1,%2,%3};"
        : "+f"(c[0]), "+f"(c[1]), "+f"(c[2]), "+f"(c[3])
        : "r"(a0), "r"(a1), "r"(a2), "r"(a3), "r"(b0), "r"(b1));
}
__device__ __forceinline__ void mma_bf16(float* c,
                                         uint32_t a0, uint32_t a1, uint32_t a2, uint32_t a3,
                                         uint32_t b0, uint32_t b1) {
    asm volatile(
        "mma.sync.aligned.m16n8k16.row.col.f32.bf16.bf16.f32 "
        "{%0,%1,%2,%3}, {%4,%5,%6,%7}, {%8,%9}, {%0,%1,%2,%3};"
        : "+f"(c[0]), "+f"(c[1]), "+f"(c[2]), "+f"(c[3])
        : "r"(a0), "r"(a1), "r"(a2), "r"(a3), "r"(b0), "r"(b1));
}
// pack two f32 -> bf16x2 (lo = first/even-k element)
__device__ __forceinline__ uint32_t bfpack(float lo, float hi) {
    uint32_t r;
    asm("cvt.rn.bf16x2.f32 %0, %1, %2;" : "=r"(r) : "f"(hi), "f"(lo));
    return r;
}
__device__ __forceinline__ float bfround(float v) {
    return __bfloat162float(__float2bfloat16(v));
}

// ---------------- kernel 1: pack adjacency to bits (transposed) + init maxE ----------------
__global__ __launch_bounds__(256) void k_pack(const int* __restrict__ adj) {
    const int nwarps = (gridDim.x * blockDim.x) >> 5;
    const int wid    = (blockIdx.x * blockDim.x + threadIdx.x) >> 5;
    const int lane   = threadIdx.x & 31;
    const int total  = BB*NN*NW;
    for (int w = wid; w < total; w += nwarps) {
        int v = adj[(size_t)w * 32 + lane];
        unsigned m = __ballot_sync(0xffffffffu, v != 0);
        if (lane == 0) {
            int b  = w / (NN*NW);
            int r  = w - b * (NN*NW);
            int i  = r / NW;
            int jw = r - i * NW;
            g_adj[((size_t)b * NW + jw) * NN + i] = m;
        }
    }
    if (blockIdx.x == 0 && threadIdx.x < BB*HH) g_maxE[threadIdx.x] = 0u;
}

// ---------------- kernel 2: Wh = x @ W via 3xBF16 mma.sync (near-fp32) ----------------
// CTA: 128 rows x 128 cols, 256 threads (8 warps: 4 M x 2 N). K in 16-chunks.
// A/B split to bf16 hi+lo; Wh = Ah*Bh + Al*Bh + Ah*Bl  (err ~1e-5 rel).
__global__ __launch_bounds__(256) void k_gemm1(const float* __restrict__ x,
                                               const float* __restrict__ W) {
    __shared__ uint32_t sAh[128*12], sAl[128*12];    // [row][k2 pad 12] bf16x2 words
    __shared__ uint32_t sBh[8*136],  sBl[8*136];     // [k2][col128 pad 136]
    const int t    = threadIdx.x;
    const int lane = t & 31;
    const int wid  = t >> 5;
    const int g    = lane >> 2;
    const int tig  = lane & 3;
    const int wy   = wid & 3;
    const int wx   = wid >> 2;
    const int rb   = blockIdx.y * 128;
    const int cb   = blockIdx.x * 128;

    const int row_a = t >> 1;            // A: loads row row_a, 8-float k half
    const int kb_a  = (t & 1) * 8;
    const int col_b = t & 127;           // B: loads col col_b, 8-float k half
    const int kb_b  = (t >> 7) * 8;
    const int col_g = cb + col_b;
    const float* wp = W + (size_t)(col_g >> 5) * (FIN*DD) + (col_g & 31);
    const float* xp = x + (size_t)(rb + row_a) * FIN + kb_a;

    float acc[2][8][4];
#pragma unroll
    for (int mi = 0; mi < 2; mi++)
#pragma unroll
        for (int nb = 0; nb < 8; nb++)
#pragma unroll
            for (int q = 0; q < 4; q++) acc[mi][nb][q] = 0.f;

    float4 va0 = *(const float4*)(xp);
    float4 va1 = *(const float4*)(xp + 4);
    float  vb[8];
#pragma unroll
    for (int i = 0; i < 8; i++) vb[i] = wp[(size_t)(kb_b + i) * DD];

    for (int ch = 0; ch < 16; ch++) {
        __syncthreads();
        {   // split + stage (bf16x2 words: pairs along k)
            float av[8] = {va0.x, va0.y, va0.z, va0.w, va1.x, va1.y, va1.z, va1.w};
#pragma unroll
            for (int i = 0; i < 4; i++) {
                float v0 = av[2*i], v1 = av[2*i+1];
                float h0 = bfround(v0), h1 = bfround(v1);
                sAh[row_a * 12 + (kb_a >> 1) + i] = bfpack(h0, h1);
                sAl[row_a * 12 + (kb_a >> 1) + i] = bfpack(v0 - h0, v1 - h1);
            }
#pragma unroll
            for (int i = 0; i < 4; i++) {
                float v0 = vb[2*i], v1 = vb[2*i+1];
                float h0 = bfround(v0), h1 = bfround(v1);
                sBh[((kb_b >> 1) + i) * 136 + col_b] = bfpack(h0, h1);
                sBl[((kb_b >> 1) + i) * 136 + col_b] = bfpack(v0 - h0, v1 - h1);
            }
        }
        __syncthreads();
        if (ch < 15) {   // prefetch next chunk
            const int kc = (ch + 1) * 16;
            va0 = *(const float4*)(xp + kc);
            va1 = *(const float4*)(xp + kc + 4);
#pragma unroll
            for (int i = 0; i < 8; i++) vb[i] = wp[(size_t)(kc + kb_b + i) * DD];
        }
        // compute: one k16 window
        uint32_t ah[2][4], al[2][4];
#pragma unroll
        for (int mi = 0; mi < 2; mi++) {
            int base = (wy*32 + mi*16 + g) * 12 + tig;
            ah[mi][0] = sAh[base];     ah[mi][1] = sAh[base + 96];
            ah[mi][2] = sAh[base + 4]; ah[mi][3] = sAh[base + 100];
            al[mi][0] = sAl[base];     al[mi][1] = sAl[base + 96];
            al[mi][2] = sAl[base + 4]; al[mi][3] = sAl[base + 100];
        }
#pragma unroll
        for (int nb = 0; nb < 8; nb++) {
            int colb = wx*64 + nb*8 + g;
            uint32_t bh0 = sBh[tig * 136 + colb], bh1 = sBh[(tig + 4) * 136 + colb];
            uint32_t bl0 = sBl[tig * 136 + colb], bl1 = sBl[(tig + 4) * 136 + colb];
#pragma unroll
            for (int mi = 0; mi < 2; mi++) {
                float* c = acc[mi][nb];
                mma_bf16(c, ah[mi][0], ah[mi][1], ah[mi][2], ah[mi][3], bh0, bh1);
                mma_bf16(c, al[mi][0], al[mi][1], al[mi][2], al[mi][3], bh0, bh1);
                mma_bf16(c, ah[mi][0], ah[mi][1], ah[mi][2], ah[mi][3], bl0, bl1);
            }
        }
    }

#pragma unroll
    for (int mi = 0; mi < 2; mi++) {
        int r0 = rb + wy*32 + mi*16 + g;
        int r1 = r0 + 8;
        int b0 = r0 >> 11, n0 = r0 & (NN-1);
        int b1 = r1 >> 11, n1 = r1 & (NN-1);
#pragma unroll
        for (int nb = 0; nb < 8; nb++) {
            int col = cb + wx*64 + nb*8 + tig*2;
            int h = col >> 5, d = col & 31;
            float* o0 = g_Wh + ((size_t)(b0*HH + h) * NN + n0) * DD + d;
            float* o1 = g_Wh + ((size_t)(b1*HH + h) * NN + n1) * DD + d;
            *(float2*)o0 = make_float2(acc[mi][nb][0], acc[mi][nb][1]);
            *(float2*)o1 = make_float2(acc[mi][nb][2], acc[mi][nb][3]);
        }
    }
}

// ---------------- kernel 3: e_src/e_dst + per-(b,h) max of e_dst ----------------
__global__ __launch_bounds__(256) void k_e(const float* __restrict__ a) {
    int idx = blockIdx.x * blockDim.x + threadIdx.x;
    int bh  = idx >> 11;
    int h   = bh & (HH - 1);
    const float* wh = g_Wh + (size_t)idx * DD;
    float es = 0.f, ed = 0.f;
#pragma unroll
    for (int d4 = 0; d4 < 8; d4++) {
        float4 w  = *(const float4*)(wh + d4 * 4);
        float4 as = *(const float4*)(a + h * 64 + d4 * 4);
        float4 ad = *(const float4*)(a + h * 64 + 32 + d4 * 4);
        es += w.x*as.x + w.y*as.y + w.z*as.z + w.w*as.w;
        ed += w.x*ad.x + w.y*ad.y + w.z*ad.z + w.w*ad.w;
    }
    g_esrc[idx] = es;
    g_edst[idx] = ed;
    unsigned u = __float_as_uint(ed);
    u = (u & 0x80000000u) ? ~u : (u | 0x80000000u);
#pragma unroll
    for (int o = 16; o; o >>= 1) {
        unsigned v = __shfl_xor_sync(0xffffffffu, u, o);
        u = (v > u) ? v : u;
    }
    if ((threadIdx.x & 31) == 0) atomicMax(&g_maxE[bh], u);
}

// ---------------- kernel 4: factorized exponentials ----------------
__global__ __launch_bounds__(256) void k_exp() {
    int idx = blockIdx.x * blockDim.x + threadIdx.x;
    int bh  = idx >> 11;
    unsigned u = g_maxE[bh];
    float maxE = (u & 0x80000000u) ? __uint_as_float(u ^ 0x80000000u)
                                   : __uint_as_float(~u);
    float es = g_esrc[idx], ed = g_edst[idx];
    float m  = es + maxE;
    m = fmaxf(m, 0.2f * m);
    g_AI[idx] = make_float4(-es, __expf(es - m), __expf(0.2f * es - m), 0.f);
    g_EJ[idx] = make_float4(ed, __expf(ed), __expf(0.2f * ed), 0.f);
}

// ---------------- kernel 5: attention via mma.sync tf32, 64-j chunks ----------------
__global__ __launch_bounds__(256) void k_attn(float* __restrict__ out) {
    __shared__ uint32_t sB[2][2048];      // 2 x 8KB, tf32 bits in fragment order (8 k8-windows)
    __shared__ float4   sEJ[2][64];
    const int t    = threadIdx.x;
    const int lane = t & 31;
    const int wid  = t >> 5;
    const int g    = lane >> 2;
    const int tig  = lane & 3;
    const int bh   = blockIdx.y;
    const int b    = bh >> 3;
    const int h    = bh & 7;
    const int i0   = blockIdx.x * 128;
    const int r0   = i0 + wid * 16 + g;
    const int r1   = r0 + 8;

    const float4 ai0 = g_AI[(size_t)bh * NN + r0];
    const float4 ai1 = g_AI[(size_t)bh * NN + r1];
    const float thr0 = ai0.x, A10 = ai0.y, A20 = ai0.z;
    const float thr1 = ai1.x, A11 = ai1.y, A21 = ai1.z;
    float rs0 = 0.f, rs1 = 0.f;
    float acc[16];
#pragma unroll
    for (int i = 0; i < 16; i++) acc[i] = 0.f;

    const float4*   whp4 = (const float4*)(g_Wh + (size_t)bh * NN * DD);
    const float4*   ejp4 = (const float4*)g_EJ + (size_t)bh * NN;
    const unsigned* adjp = g_adj + (size_t)b * NW * NN;

    // staging geometry: thread stages j-row sj = t>>2, d range (t&3)*8 .. +7
    const int sj    = t >> 2;
    const int sw    = sj >> 3;            // k8 window within chunk
    const int sk    = sj & 3;
    const int shalf = (sj >> 2) & 1;
    const int dq    = t & 3;              // d-block of 8

    // ---- prologue: stage chunk 0 (j 0..63) ----
    {
        float4 v0 = whp4[(size_t)sj * 8 + dq * 2];
        float4 v1 = whp4[(size_t)sj * 8 + dq * 2 + 1];
        if (t < 64) sEJ[0][t] = ejp4[t];
        const float* vv = &v0.x;
#pragma unroll
        for (int u = 0; u < 8; u++) {
            int idx = ((sw << 2) + dq) * 64 + (u << 3) + sk * 2 + shalf;
            sB[0][idx] = f2tf(u < 4 ? vv[u] : (&v1.x)[u - 4]);
        }
    }
    unsigned awa0 = adjp[r0],      awb0 = adjp[(size_t)NN + r0];
    unsigned awa1 = adjp[r1],      awb1 = adjp[(size_t)NN + r1];
    __syncthreads();

    for (int c = 0; c < 32; c++) {
        const int buf = c & 1;
        const int cn = (c + 1 < 32) ? c + 1 : 0;
        // prefetch chunk cn
        float4 v0 = whp4[((size_t)cn * 64 + sj) * 8 + dq * 2];
        float4 v1 = whp4[((size_t)cn * 64 + sj) * 8 + dq * 2 + 1];
        float4 vE = make_float4(0.f, 0.f, 0.f, 0.f);
        if (t < 64) vE = ejp4[cn * 64 + t];
        unsigned nwa0 = adjp[(size_t)(2*cn)   * NN + r0];
        unsigned nwb0 = adjp[(size_t)(2*cn+1) * NN + r0];
        unsigned nwa1 = adjp[(size_t)(2*cn)   * NN + r1];
        unsigned nwb1 = adjp[(size_t)(2*cn+1) * NN + r1];

        const float4*   EJ = sEJ[buf];
        const uint32_t* Bf = sB[buf];
#pragma unroll
        for (int w = 0; w < 8; w++) {
            const unsigned w0 = (w < 4) ? awa0 : awb0;
            const unsigned w1 = (w < 4) ? awa1 : awb1;
            float4 ev0 = EJ[w * 8 + tig];
            float4 ev1 = EJ[w * 8 + tig + 4];
            float p0 = (ev0.x > thr0) ? A10 * ev0.y : A20 * ev0.z;
            float p1 = (ev0.x > thr1) ? A11 * ev0.y : A21 * ev0.z;
            float p2 = (ev1.x > thr0) ? A10 * ev1.y : A20 * ev1.z;
            float p3 = (ev1.x > thr1) ? A11 * ev1.y : A21 * ev1.z;
            const int jb = (w & 3) * 8 + tig;
            if (!((w0 >> jb) & 1u))       p0 = 0.f;
            if (!((w1 >> jb) & 1u))       p1 = 0.f;
            if (!((w0 >> (jb + 4)) & 1u)) p2 = 0.f;
            if (!((w1 >> (jb + 4)) & 1u)) p3 = 0.f;
            rs0 += p0 + p2;
            rs1 += p1 + p3;
            uint32_t a0 = f2tf(p0), a1 = f2tf(p1), a2 = f2tf(p2), a3 = f2tf(p3);
#pragma unroll
            for (int nb = 0; nb < 4; nb++) {
                uint2 bb = *(const uint2*)&Bf[((w << 2) + nb) * 64 + lane * 2];
                mma_tf32(acc + nb * 4, a0, a1, a2, a3, bb.x, bb.y);
            }
        }

        // stage chunk cn into the other buffer
        const int nbuf = buf ^ 1;
        if (t < 64) sEJ[nbuf][t] = vE;
        {
            const float* vv = &v0.x;
#pragma unroll
            for (int u = 0; u < 8; u++) {
                int idx = ((sw << 2) + dq) * 64 + (u << 3) + sk * 2 + shalf;
                sB[nbuf][idx] = f2tf(u < 4 ? vv[u] : (&v1.x)[u - 4]);
            }
        }
        awa0 = nwa0; awb0 = nwb0; awa1 = nwa1; awb1 = nwb1;
        __syncthreads();
    }

    rs0 += __shfl_xor_sync(0xffffffffu, rs0, 1);
    rs0 += __shfl_xor_sync(0xffffffffu, rs0, 2);
    rs1 += __shfl_xor_sync(0xffffffffu, rs1, 1);
    rs1 += __shfl_xor_sync(0xffffffffu, rs1, 2);
    const float inv0 = 1.0f / rs0;
    const float inv1 = 1.0f / rs1;

    float* o0 = out + ((size_t)(b * NN + r0)) * (HH * DD) + h * DD + tig * 2;
    float* o1 = out + ((size_t)(b * NN + r1)) * (HH * DD) + h * DD + tig * 2;
#pragma unroll
    for (int nb = 0; nb < 4; nb++) {
        *(float2*)(o0 + nb * 8) = make_float2(acc[nb*4 + 0] * inv0, acc[nb*4 + 1] * inv0);
        *(float2*)(o1 + nb * 8) = make_float2(acc[nb*4 + 2] * inv1, acc[nb*4 + 3] * inv1);
    }
}

// ---------------- launch ----------------
extern "C" void kernel_launch(void* const* d_in, const int* in_sizes, int n_in,
                              void* d_out, int out_size) {
    const float* x   = (const float*)d_in[0];
    const int*   adj = (const int*)  d_in[1];
    const float* W   = (const float*)d_in[2];
    const float* a   = (const float*)d_in[3];
    float* out = (float*)d_out;

    k_pack <<<2048, 256>>>(adj);
    k_gemm1<<<dim3(2, 64), 256>>>(x, W);
    k_e    <<<(BB*HH*NN)/256, 256>>>(a);
    k_exp  <<<(BB*HH*NN)/256, 256>>>();
    k_attn <<<dim3(NN/128, BB*HH), 256>>>(out);
}

// round 11
// speedup vs baseline: 2.7441x; 1.2019x over previous
#include <cuda_runtime.h>
#include <cuda_bf16.h>
#include <cstdint>

#define BB  4
#define NN  2048
#define FIN 256
#define HH  8
#define DD  32
#define NW  (NN/32)   // 64 adj words per row

// ---------------- device scratch (no allocations allowed) ----------------
__device__ float    g_Wh[BB*HH*NN*DD];     // [b][h][n][d]  8.4MB
__device__ float    g_esrc[BB*HH*NN];
__device__ float    g_edst[BB*HH*NN];
__device__ float4   g_AI[BB*HH*NN];        // (-e_src, A1, A2, 0)
__device__ float4   g_EJ[BB*HH*NN];        // (e_dst,  E1, E2, 0)
__device__ unsigned g_maxE[BB*HH];
__device__ unsigned g_adj[BB*NN*NW];       // packed adjacency bits, TRANSPOSED [b][jw][i]

// ---------------- mma.sync helpers (sm_80+ portable PTX) ----------------
__device__ __forceinline__ void mma_bf16(float* c,
                                         uint32_t a0, uint32_t a1, uint32_t a2, uint32_t a3,
                                         uint32_t b0, uint32_t b1) {
    asm volatile(
        "mma.sync.aligned.m16n8k16.row.col.f32.bf16.bf16.f32 "
        "{%0,%1,%2,%3}, {%4,%5,%6,%7}, {%8,%9}, {%0,%1,%2,%3};"
        : "+f"(c[0]), "+f"(c[1]), "+f"(c[2]), "+f"(c[3])
        : "r"(a0), "r"(a1), "r"(a2), "r"(a3), "r"(b0), "r"(b1));
}
__device__ __forceinline__ void mma_f16(float* c,
                                        uint32_t a0, uint32_t a1, uint32_t a2, uint32_t a3,
                                        uint32_t b0, uint32_t b1) {
    asm volatile(
        "mma.sync.aligned.m16n8k16.row.col.f32.f16.f16.f32 "
        "{%0,%1,%2,%3}, {%4,%5,%6,%7}, {%8,%9}, {%0,%1,%2,%3};"
        : "+f"(c[0]), "+f"(c[1]), "+f"(c[2]), "+f"(c[3])
        : "r"(a0), "r"(a1), "r"(a2), "r"(a3), "r"(b0), "r"(b1));
}
// pack two f32 -> bf16x2 / f16x2 (first arg -> LOW half = even-k element)
__device__ __forceinline__ uint32_t bfpack(float lo, float hi) {
    uint32_t r;
    asm("cvt.rn.bf16x2.f32 %0, %1, %2;" : "=r"(r) : "f"(hi), "f"(lo));
    return r;
}
__device__ __forceinline__ uint32_t h2pack(float lo, float hi) {
    uint32_t r;
    asm("cvt.rn.f16x2.f32 %0, %1, %2;" : "=r"(r) : "f"(hi), "f"(lo));
    return r;
}
__device__ __forceinline__ float bfround(float v) {
    return __bfloat162float(__float2bfloat16(v));
}

// ---------------- kernel 1: pack adjacency to bits (transposed) + init maxE ----------------
__global__ __launch_bounds__(256) void k_pack(const int* __restrict__ adj) {
    const int nwarps = (gridDim.x * blockDim.x) >> 5;
    const int wid    = (blockIdx.x * blockDim.x + threadIdx.x) >> 5;
    const int lane   = threadIdx.x & 31;
    const int total  = BB*NN*NW;
    for (int w = wid; w < total; w += nwarps) {
        int v = adj[(size_t)w * 32 + lane];
        unsigned m = __ballot_sync(0xffffffffu, v != 0);
        if (lane == 0) {
            int b  = w / (NN*NW);
            int r  = w - b * (NN*NW);
            int i  = r / NW;
            int jw = r - i * NW;
            g_adj[((size_t)b * NW + jw) * NN + i] = m;
        }
    }
    if (blockIdx.x == 0 && threadIdx.x < BB*HH) g_maxE[threadIdx.x] = 0u;
}

// ---------------- kernel 2: Wh = x @ W via 3xBF16 mma.sync (near-fp32) ----------------
__global__ __launch_bounds__(256) void k_gemm1(const float* __restrict__ x,
                                               const float* __restrict__ W) {
    __shared__ uint32_t sAh[128*12], sAl[128*12];    // [row][k2 pad 12] bf16x2 words
    __shared__ uint32_t sBh[8*136],  sBl[8*136];     // [k2][col128 pad 136]
    const int t    = threadIdx.x;
    const int lane = t & 31;
    const int wid  = t >> 5;
    const int g    = lane >> 2;
    const int tig  = lane & 3;
    const int wy   = wid & 3;
    const int wx   = wid >> 2;
    const int rb   = blockIdx.y * 128;
    const int cb   = blockIdx.x * 128;

    const int row_a = t >> 1;
    const int kb_a  = (t & 1) * 8;
    const int col_b = t & 127;
    const int kb_b  = (t >> 7) * 8;
    const int col_g = cb + col_b;
    const float* wp = W + (size_t)(col_g >> 5) * (FIN*DD) + (col_g & 31);
    const float* xp = x + (size_t)(rb + row_a) * FIN + kb_a;

    float acc[2][8][4];
#pragma unroll
    for (int mi = 0; mi < 2; mi++)
#pragma unroll
        for (int nb = 0; nb < 8; nb++)
#pragma unroll
            for (int q = 0; q < 4; q++) acc[mi][nb][q] = 0.f;

    float4 va0 = *(const float4*)(xp);
    float4 va1 = *(const float4*)(xp + 4);
    float  vb[8];
#pragma unroll
    for (int i = 0; i < 8; i++) vb[i] = wp[(size_t)(kb_b + i) * DD];

    for (int ch = 0; ch < 16; ch++) {
        __syncthreads();
        {
            float av[8] = {va0.x, va0.y, va0.z, va0.w, va1.x, va1.y, va1.z, va1.w};
#pragma unroll
            for (int i = 0; i < 4; i++) {
                float v0 = av[2*i], v1 = av[2*i+1];
                float h0 = bfround(v0), h1 = bfround(v1);
                sAh[row_a * 12 + (kb_a >> 1) + i] = bfpack(h0, h1);
                sAl[row_a * 12 + (kb_a >> 1) + i] = bfpack(v0 - h0, v1 - h1);
            }
#pragma unroll
            for (int i = 0; i < 4; i++) {
                float v0 = vb[2*i], v1 = vb[2*i+1];
                float h0 = bfround(v0), h1 = bfround(v1);
                sBh[((kb_b >> 1) + i) * 136 + col_b] = bfpack(h0, h1);
                sBl[((kb_b >> 1) + i) * 136 + col_b] = bfpack(v0 - h0, v1 - h1);
            }
        }
        __syncthreads();
        if (ch < 15) {
            const int kc = (ch + 1) * 16;
            va0 = *(const float4*)(xp + kc);
            va1 = *(const float4*)(xp + kc + 4);
#pragma unroll
            for (int i = 0; i < 8; i++) vb[i] = wp[(size_t)(kc + kb_b + i) * DD];
        }
        uint32_t ah[2][4], al[2][4];
#pragma unroll
        for (int mi = 0; mi < 2; mi++) {
            int base = (wy*32 + mi*16 + g) * 12 + tig;
            ah[mi][0] = sAh[base];     ah[mi][1] = sAh[base + 96];
            ah[mi][2] = sAh[base + 4]; ah[mi][3] = sAh[base + 100];
            al[mi][0] = sAl[base];     al[mi][1] = sAl[base + 96];
            al[mi][2] = sAl[base + 4]; al[mi][3] = sAl[base + 100];
        }
#pragma unroll
        for (int nb = 0; nb < 8; nb++) {
            int colb = wx*64 + nb*8 + g;
            uint32_t bh0 = sBh[tig * 136 + colb], bh1 = sBh[(tig + 4) * 136 + colb];
            uint32_t bl0 = sBl[tig * 136 + colb], bl1 = sBl[(tig + 4) * 136 + colb];
#pragma unroll
            for (int mi = 0; mi < 2; mi++) {
                float* c = acc[mi][nb];
                mma_bf16(c, ah[mi][0], ah[mi][1], ah[mi][2], ah[mi][3], bh0, bh1);
                mma_bf16(c, al[mi][0], al[mi][1], al[mi][2], al[mi][3], bh0, bh1);
                mma_bf16(c, ah[mi][0], ah[mi][1], ah[mi][2], ah[mi][3], bl0, bl1);
            }
        }
    }

#pragma unroll
    for (int mi = 0; mi < 2; mi++) {
        int r0 = rb + wy*32 + mi*16 + g;
        int r1 = r0 + 8;
        int b0 = r0 >> 11, n0 = r0 & (NN-1);
        int b1 = r1 >> 11, n1 = r1 & (NN-1);
#pragma unroll
        for (int nb = 0; nb < 8; nb++) {
            int col = cb + wx*64 + nb*8 + tig*2;
            int h = col >> 5, d = col & 31;
            float* o0 = g_Wh + ((size_t)(b0*HH + h) * NN + n0) * DD + d;
            float* o1 = g_Wh + ((size_t)(b1*HH + h) * NN + n1) * DD + d;
            *(float2*)o0 = make_float2(acc[mi][nb][0], acc[mi][nb][1]);
            *(float2*)o1 = make_float2(acc[mi][nb][2], acc[mi][nb][3]);
        }
    }
}

// ---------------- kernel 3: e_src/e_dst + per-(b,h) max of e_dst ----------------
__global__ __launch_bounds__(256) void k_e(const float* __restrict__ a) {
    int idx = blockIdx.x * blockDim.x + threadIdx.x;
    int bh  = idx >> 11;
    int h   = bh & (HH - 1);
    const float* wh = g_Wh + (size_t)idx * DD;
    float es = 0.f, ed = 0.f;
#pragma unroll
    for (int d4 = 0; d4 < 8; d4++) {
        float4 w  = *(const float4*)(wh + d4 * 4);
        float4 as = *(const float4*)(a + h * 64 + d4 * 4);
        float4 ad = *(const float4*)(a + h * 64 + 32 + d4 * 4);
        es += w.x*as.x + w.y*as.y + w.z*as.z + w.w*as.w;
        ed += w.x*ad.x + w.y*ad.y + w.z*ad.z + w.w*ad.w;
    }
    g_esrc[idx] = es;
    g_edst[idx] = ed;
    unsigned u = __float_as_uint(ed);
    u = (u & 0x80000000u) ? ~u : (u | 0x80000000u);
#pragma unroll
    for (int o = 16; o; o >>= 1) {
        unsigned v = __shfl_xor_sync(0xffffffffu, u, o);
        u = (v > u) ? v : u;
    }
    if ((threadIdx.x & 31) == 0) atomicMax(&g_maxE[bh], u);
}

// ---------------- kernel 4: factorized exponentials ----------------
__global__ __launch_bounds__(256) void k_exp() {
    int idx = blockIdx.x * blockDim.x + threadIdx.x;
    int bh  = idx >> 11;
    unsigned u = g_maxE[bh];
    float maxE = (u & 0x80000000u) ? __uint_as_float(u ^ 0x80000000u)
                                   : __uint_as_float(~u);
    float es = g_esrc[idx], ed = g_edst[idx];
    float m  = es + maxE;
    m = fmaxf(m, 0.2f * m);
    g_AI[idx] = make_float4(-es, __expf(es - m), __expf(0.2f * es - m), 0.f);
    g_EJ[idx] = make_float4(ed, __expf(ed), __expf(0.2f * ed), 0.f);
}

// ---------------- kernel 5: attention via mma.sync fp16 k16, 64-j chunks ----------------
// fp16 mantissa (10 bits) == tf32 mantissa, so precision matches the tf32 version,
// but each mma consumes k=16 -> half the HMMA instruction count.
__global__ __launch_bounds__(256) void k_attn(float* __restrict__ out) {
    __shared__ uint32_t sB[2][1024];      // 2 x 4KB fp16x2 words, fragment order, nb-XOR swizzled
    __shared__ float4   sEJ[2][64];
    const int t    = threadIdx.x;
    const int lane = t & 31;
    const int wid  = t >> 5;
    const int g    = lane >> 2;
    const int tig  = lane & 3;
    const int bh   = blockIdx.y;
    const int b    = bh >> 3;
    const int h    = bh & 7;
    const int i0   = blockIdx.x * 128;
    const int r0   = i0 + wid * 16 + g;
    const int r1   = r0 + 8;

    const float4 ai0 = g_AI[(size_t)bh * NN + r0];
    const float4 ai1 = g_AI[(size_t)bh * NN + r1];
    const float thr0 = ai0.x, A10 = ai0.y, A20 = ai0.z;
    const float thr1 = ai1.x, A11 = ai1.y, A21 = ai1.z;
    float rs0 = 0.f, rs1 = 0.f;
    float acc[16];
#pragma unroll
    for (int i = 0; i < 16; i++) acc[i] = 0.f;

    const float4*   whp4 = (const float4*)(g_Wh + (size_t)bh * NN * DD);
    const float4*   ejp4 = (const float4*)g_EJ + (size_t)bh * NN;
    const unsigned* adjp = g_adj + (size_t)b * NW * NN;

    // staging geometry: thread -> (k16 window, j-pair, d-quad)
    const int sw_w  = t >> 6;            // 0..3
    const int sw_kp = (t >> 3) & 7;      // j-pair within window
    const int sw_q  = t & 7;             // d-quad (4 floats)
    const int sw_tg = sw_kp & 3;
    const int sw_hb = sw_kp >> 2;
    const int sw_nb = sw_q >> 1;
    const int sw_j  = sw_w * 16 + sw_kp * 2;   // even j within chunk
    const int sw_bs = (sw_w * 4 + sw_nb) * 64; // word-block base
    const int sw_xs = sw_nb << 3;              // XOR swizzle

    // ---- prologue: stage chunk 0 (j 0..63) ----
    {
        float4 v0 = whp4[(size_t)sw_j * 8 + sw_q];
        float4 v1 = whp4[(size_t)(sw_j + 1) * 8 + sw_q];
        if (t < 64) sEJ[0][t] = ejp4[t];
#pragma unroll
        for (int u = 0; u < 4; u++) {
            int dg   = (sw_q & 1) * 4 + u;
            int idx  = sw_bs + ((((dg * 4 + sw_tg) * 2) + sw_hb) ^ sw_xs);
            sB[0][idx] = h2pack((&v0.x)[u], (&v1.x)[u]);
        }
    }
    unsigned awa0 = adjp[r0], awb0 = adjp[(size_t)NN + r0];
    unsigned awa1 = adjp[r1], awb1 = adjp[(size_t)NN + r1];
    __syncthreads();

    for (int c = 0; c < 32; c++) {
        const int buf = c & 1;
        const int cn  = (c + 1 < 32) ? c + 1 : 0;
        // prefetch chunk cn
        float4 v0 = whp4[((size_t)cn * 64 + sw_j) * 8 + sw_q];
        float4 v1 = whp4[((size_t)cn * 64 + sw_j + 1) * 8 + sw_q];
        float4 vE = make_float4(0.f, 0.f, 0.f, 0.f);
        if (t < 64) vE = ejp4[cn * 64 + t];
        unsigned nwa0 = adjp[(size_t)(2*cn)   * NN + r0];
        unsigned nwb0 = adjp[(size_t)(2*cn+1) * NN + r0];
        unsigned nwa1 = adjp[(size_t)(2*cn)   * NN + r1];
        unsigned nwb1 = adjp[(size_t)(2*cn+1) * NN + r1];

        const float4*   EJ = sEJ[buf];
        const uint32_t* Bf = sB[buf];
#pragma unroll
        for (int w = 0; w < 4; w++) {          // 4 k16 windows of 16 j
            const unsigned wd0 = (w < 2) ? awa0 : awb0;
            const unsigned wd1 = (w < 2) ? awa1 : awb1;
            const int bb = (w & 1) * 16 + 2 * tig;
            float4 evA = EJ[w*16 + 2*tig];
            float4 evB = EJ[w*16 + 2*tig + 1];
            float4 evC = EJ[w*16 + 2*tig + 8];
            float4 evD = EJ[w*16 + 2*tig + 9];
            float p00 = (evA.x > thr0) ? A10 * evA.y : A20 * evA.z;
            float p10 = (evA.x > thr1) ? A11 * evA.y : A21 * evA.z;
            float p01 = (evB.x > thr0) ? A10 * evB.y : A20 * evB.z;
            float p11 = (evB.x > thr1) ? A11 * evB.y : A21 * evB.z;
            float p02 = (evC.x > thr0) ? A10 * evC.y : A20 * evC.z;
            float p12 = (evC.x > thr1) ? A11 * evC.y : A21 * evC.z;
            float p03 = (evD.x > thr0) ? A10 * evD.y : A20 * evD.z;
            float p13 = (evD.x > thr1) ? A11 * evD.y : A21 * evD.z;
            if (!((wd0 >> bb)       & 1u)) p00 = 0.f;
            if (!((wd1 >> bb)       & 1u)) p10 = 0.f;
            if (!((wd0 >> (bb + 1)) & 1u)) p01 = 0.f;
            if (!((wd1 >> (bb + 1)) & 1u)) p11 = 0.f;
            if (!((wd0 >> (bb + 8)) & 1u)) p02 = 0.f;
            if (!((wd1 >> (bb + 8)) & 1u)) p12 = 0.f;
            if (!((wd0 >> (bb + 9)) & 1u)) p03 = 0.f;
            if (!((wd1 >> (bb + 9)) & 1u)) p13 = 0.f;
            rs0 += (p00 + p01) + (p02 + p03);
            rs1 += (p10 + p11) + (p12 + p13);
            uint32_t a0 = h2pack(p00, p01);
            uint32_t a1 = h2pack(p10, p11);
            uint32_t a2 = h2pack(p02, p03);
            uint32_t a3 = h2pack(p12, p13);
#pragma unroll
            for (int nb = 0; nb < 4; nb++) {
                uint2 bb2 = *(const uint2*)&Bf[(w*4 + nb)*64 + ((lane*2) ^ (nb << 3))];
                mma_f16(acc + nb * 4, a0, a1, a2, a3, bb2.x, bb2.y);
            }
        }

        // stage chunk cn into the other buffer
        const int nbuf = buf ^ 1;
        if (t < 64) sEJ[nbuf][t] = vE;
#pragma unroll
        for (int u = 0; u < 4; u++) {
            int dg  = (sw_q & 1) * 4 + u;
            int idx = sw_bs + ((((dg * 4 + sw_tg) * 2) + sw_hb) ^ sw_xs);
            sB[nbuf][idx] = h2pack((&v0.x)[u], (&v1.x)[u]);
        }
        awa0 = nwa0; awb0 = nwb0; awa1 = nwa1; awb1 = nwb1;
        __syncthreads();
    }

    rs0 += __shfl_xor_sync(0xffffffffu, rs0, 1);
    rs0 += __shfl_xor_sync(0xffffffffu, rs0, 2);
    rs1 += __shfl_xor_sync(0xffffffffu, rs1, 1);
    rs1 += __shfl_xor_sync(0xffffffffu, rs1, 2);
    const float inv0 = 1.0f / rs0;
    const float inv1 = 1.0f / rs1;

    float* o0 = out + ((size_t)(b * NN + r0)) * (HH * DD) + h * DD + tig * 2;
    float* o1 = out + ((size_t)(b * NN + r1)) * (HH * DD) + h * DD + tig * 2;
#pragma unroll
    for (int nb = 0; nb < 4; nb++) {
        *(float2*)(o0 + nb * 8) = make_float2(acc[nb*4 + 0] * inv0, acc[nb*4 + 1] * inv0);
        *(float2*)(o1 + nb * 8) = make_float2(acc[nb*4 + 2] * inv1, acc[nb*4 + 3] * inv1);
    }
}

// ---------------- launch ----------------
extern "C" void kernel_launch(void* const* d_in, const int* in_sizes, int n_in,
                              void* d_out, int out_size) {
    const float* x   = (const float*)d_in[0];
    const int*   adj = (const int*)  d_in[1];
    const float* W   = (const float*)d_in[2];
    const float* a   = (const float*)d_in[3];
    float* out = (float*)d_out;

    k_pack <<<2048, 256>>>(adj);
    k_gemm1<<<dim3(2, 64), 256>>>(x, W);
    k_e    <<<(BB*HH*NN)/256, 256>>>(a);
    k_exp  <<<(BB*HH*NN)/256, 256>>>();
    k_attn <<<dim3(NN/128, BB*HH), 256>>>(out);
}

// round 12
// speedup vs baseline: 3.0962x; 1.1283x over previous
#include <cuda_runtime.h>
#include <cuda_bf16.h>
#include <cstdint>

#define BB  4
#define NN  2048
#define FIN 256
#define HH  8
#define DD  32
#define NW  (NN/32)   // 64 adj words per row

// ---------------- device scratch (no allocations allowed) ----------------
__device__ float    g_Wh[BB*HH*NN*DD];     // [b][h][n][d]  8.4MB
__device__ float2   g_AI2[BB*HH*NN];       // (A1', A2') per row i
__device__ float    g_E1[BB*HH*NN];        // exp(e_dst - maxE)
__device__ float    g_E2[BB*HH*NN];        // exp(0.2(e_dst - maxE))
__device__ unsigned g_adj[BB*NN*NW];       // packed adjacency bits, TRANSPOSED [b][jw][i]

// ---------------- mma.sync / packed helpers (portable PTX) ----------------
__device__ __forceinline__ void mma_bf16(float* c,
                                         uint32_t a0, uint32_t a1, uint32_t a2, uint32_t a3,
                                         uint32_t b0, uint32_t b1) {
    asm volatile(
        "mma.sync.aligned.m16n8k16.row.col.f32.bf16.bf16.f32 "
        "{%0,%1,%2,%3}, {%4,%5,%6,%7}, {%8,%9}, {%0,%1,%2,%3};"
        : "+f"(c[0]), "+f"(c[1]), "+f"(c[2]), "+f"(c[3])
        : "r"(a0), "r"(a1), "r"(a2), "r"(a3), "r"(b0), "r"(b1));
}
__device__ __forceinline__ void mma_f16(float* c,
                                        uint32_t a0, uint32_t a1, uint32_t a2, uint32_t a3,
                                        uint32_t b0, uint32_t b1) {
    asm volatile(
        "mma.sync.aligned.m16n8k16.row.col.f32.f16.f16.f32 "
        "{%0,%1,%2,%3}, {%4,%5,%6,%7}, {%8,%9}, {%0,%1,%2,%3};"
        : "+f"(c[0]), "+f"(c[1]), "+f"(c[2]), "+f"(c[3])
        : "r"(a0), "r"(a1), "r"(a2), "r"(a3), "r"(b0), "r"(b1));
}
__device__ __forceinline__ uint32_t bfpack(float lo, float hi) {
    uint32_t r;
    asm("cvt.rn.bf16x2.f32 %0, %1, %2;" : "=r"(r) : "f"(hi), "f"(lo));
    return r;
}
__device__ __forceinline__ uint32_t h2pack(float lo, float hi) {
    uint32_t r;
    asm("cvt.rn.f16x2.f32 %0, %1, %2;" : "=r"(r) : "f"(hi), "f"(lo));
    return r;
}
__device__ __forceinline__ float bfround(float v) {
    return __bfloat162float(__float2bfloat16(v));
}
__device__ __forceinline__ unsigned long long pk2(float lo, float hi) {
    unsigned long long r;
    asm("mov.b64 %0, {%1, %2};" : "=l"(r) : "f"(lo), "f"(hi));
    return r;
}
__device__ __forceinline__ float2 upk2(unsigned long long v) {
    float2 r;
    asm("mov.b64 {%0, %1}, %2;" : "=f"(r.x), "=f"(r.y) : "l"(v));
    return r;
}
// packed f32x2 multiply via the proven fma.rn.f32x2 (addend = 0)
__device__ __forceinline__ unsigned long long fmul2(unsigned long long a,
                                                    unsigned long long b) {
    unsigned long long r, z = 0ull;
    asm("fma.rn.f32x2 %0, %1, %2, %3;" : "=l"(r) : "l"(a), "l"(b), "l"(z));
    return r;
}

// ---------------- kernel 1: pack adjacency to bits (transposed) ----------------
__global__ __launch_bounds__(256) void k_pack(const int* __restrict__ adj) {
    const int nwarps = (gridDim.x * blockDim.x) >> 5;
    const int wid    = (blockIdx.x * blockDim.x + threadIdx.x) >> 5;
    const int lane   = threadIdx.x & 31;
    const int total  = BB*NN*NW;
    for (int w = wid; w < total; w += nwarps) {
        int v = adj[(size_t)w * 32 + lane];
        unsigned m = __ballot_sync(0xffffffffu, v != 0);
        if (lane == 0) {
            int b  = w / (NN*NW);
            int r  = w - b * (NN*NW);
            int i  = r / NW;
            int jw = r - i * NW;
            g_adj[((size_t)b * NW + jw) * NN + i] = m;
        }
    }
}

// ---------------- kernel 2: Wh = x @ W via 3xBF16 mma.sync (near-fp32) ----------------
__global__ __launch_bounds__(256) void k_gemm1(const float* __restrict__ x,
                                               const float* __restrict__ W) {
    __shared__ uint32_t sAh[128*12], sAl[128*12];    // [row][k2 pad 12] bf16x2 words
    __shared__ uint32_t sBh[8*136],  sBl[8*136];     // [k2][col128 pad 136]
    const int t    = threadIdx.x;
    const int lane = t & 31;
    const int wid  = t >> 5;
    const int g    = lane >> 2;
    const int tig  = lane & 3;
    const int wy   = wid & 3;
    const int wx   = wid >> 2;
    const int rb   = blockIdx.y * 128;
    const int cb   = blockIdx.x * 128;

    const int row_a = t >> 1;
    const int kb_a  = (t & 1) * 8;
    const int col_b = t & 127;
    const int kb_b  = (t >> 7) * 8;
    const int col_g = cb + col_b;
    const float* wp = W + (size_t)(col_g >> 5) * (FIN*DD) + (col_g & 31);
    const float* xp = x + (size_t)(rb + row_a) * FIN + kb_a;

    float acc[2][8][4];
#pragma unroll
    for (int mi = 0; mi < 2; mi++)
#pragma unroll
        for (int nb = 0; nb < 8; nb++)
#pragma unroll
            for (int q = 0; q < 4; q++) acc[mi][nb][q] = 0.f;

    float4 va0 = *(const float4*)(xp);
    float4 va1 = *(const float4*)(xp + 4);
    float  vb[8];
#pragma unroll
    for (int i = 0; i < 8; i++) vb[i] = wp[(size_t)(kb_b + i) * DD];

    for (int ch = 0; ch < 16; ch++) {
        __syncthreads();
        {
            float av[8] = {va0.x, va0.y, va0.z, va0.w, va1.x, va1.y, va1.z, va1.w};
#pragma unroll
            for (int i = 0; i < 4; i++) {
                float v0 = av[2*i], v1 = av[2*i+1];
                float h0 = bfround(v0), h1 = bfround(v1);
                sAh[row_a * 12 + (kb_a >> 1) + i] = bfpack(h0, h1);
                sAl[row_a * 12 + (kb_a >> 1) + i] = bfpack(v0 - h0, v1 - h1);
            }
#pragma unroll
            for (int i = 0; i < 4; i++) {
                float v0 = vb[2*i], v1 = vb[2*i+1];
                float h0 = bfround(v0), h1 = bfround(v1);
                sBh[((kb_b >> 1) + i) * 136 + col_b] = bfpack(h0, h1);
                sBl[((kb_b >> 1) + i) * 136 + col_b] = bfpack(v0 - h0, v1 - h1);
            }
        }
        __syncthreads();
        if (ch < 15) {
            const int kc = (ch + 1) * 16;
            va0 = *(const float4*)(xp + kc);
            va1 = *(const float4*)(xp + kc + 4);
#pragma unroll
            for (int i = 0; i < 8; i++) vb[i] = wp[(size_t)(kc + kb_b + i) * DD];
        }
        uint32_t ah[2][4], al[2][4];
#pragma unroll
        for (int mi = 0; mi < 2; mi++) {
            int base = (wy*32 + mi*16 + g) * 12 + tig;
            ah[mi][0] = sAh[base];     ah[mi][1] = sAh[base + 96];
            ah[mi][2] = sAh[base + 4]; ah[mi][3] = sAh[base + 100];
            al[mi][0] = sAl[base];     al[mi][1] = sAl[base + 96];
            al[mi][2] = sAl[base + 4]; al[mi][3] = sAl[base + 100];
        }
#pragma unroll
        for (int nb = 0; nb < 8; nb++) {
            int colb = wx*64 + nb*8 + g;
            uint32_t bh0 = sBh[tig * 136 + colb], bh1 = sBh[(tig + 4) * 136 + colb];
            uint32_t bl0 = sBl[tig * 136 + colb], bl1 = sBl[(tig + 4) * 136 + colb];
#pragma unroll
            for (int mi = 0; mi < 2; mi++) {
                float* c = acc[mi][nb];
                mma_bf16(c, ah[mi][0], ah[mi][1], ah[mi][2], ah[mi][3], bh0, bh1);
                mma_bf16(c, al[mi][0], al[mi][1], al[mi][2], al[mi][3], bh0, bh1);
                mma_bf16(c, ah[mi][0], ah[mi][1], ah[mi][2], ah[mi][3], bl0, bl1);
            }
        }
    }

#pragma unroll
    for (int mi = 0; mi < 2; mi++) {
        int r0 = rb + wy*32 + mi*16 + g;
        int r1 = r0 + 8;
        int b0 = r0 >> 11, n0 = r0 & (NN-1);
        int b1 = r1 >> 11, n1 = r1 & (NN-1);
#pragma unroll
        for (int nb = 0; nb < 8; nb++) {
            int col = cb + wx*64 + nb*8 + tig*2;
            int h = col >> 5, d = col & 31;
            float* o0 = g_Wh + ((size_t)(b0*HH + h) * NN + n0) * DD + d;
            float* o1 = g_Wh + ((size_t)(b1*HH + h) * NN + n1) * DD + d;
            *(float2*)o0 = make_float2(acc[mi][nb][0], acc[mi][nb][1]);
            *(float2*)o1 = make_float2(acc[mi][nb][2], acc[mi][nb][3]);
        }
    }
}

// ---------------- kernel 3: fused e/max/exp — one CTA per (b,h) ----------------
// thread t handles rows t, t+512, t+1024, t+1536. Block-local max (no atomics).
// Emits normalized factors (all <= 1, fp16-safe downstream):
//   A1 = exp(es+maxE-m), A2 = exp(0.2(es+maxE)-m), m = max(sm, 0.2 sm), sm = es+maxE
//   E1 = exp(ed-maxE),   E2 = exp(0.2(ed-maxE))
__global__ __launch_bounds__(512) void k_ee(const float* __restrict__ a) {
    __shared__ float sA[64];
    __shared__ float sRed[16];
    const int bh = blockIdx.x;
    const int h  = bh & 7;
    const int t  = threadIdx.x;
    if (t < 16) ((float4*)sA)[t] = ((const float4*)(a + h * 64))[t];
    __syncthreads();

    float es[4], ed[4];
    float lmax = -1e30f;
    const float* whb = g_Wh + (size_t)bh * NN * DD;
#pragma unroll
    for (int k = 0; k < 4; k++) {
        const int r = k * 512 + t;
        const float4* wr = (const float4*)(whb + (size_t)r * DD);
        float s0 = 0.f, s1 = 0.f;
#pragma unroll
        for (int q = 0; q < 8; q++) {
            float4 w  = wr[q];
            float4 as = ((const float4*)sA)[q];
            float4 ad = ((const float4*)sA)[8 + q];
            s0 += w.x*as.x + w.y*as.y + w.z*as.z + w.w*as.w;
            s1 += w.x*ad.x + w.y*ad.y + w.z*ad.z + w.w*ad.w;
        }
        es[k] = s0; ed[k] = s1;
        lmax = fmaxf(lmax, s1);
    }
#pragma unroll
    for (int o = 16; o; o >>= 1)
        lmax = fmaxf(lmax, __shfl_xor_sync(0xffffffffu, lmax, o));
    if ((t & 31) == 0) sRed[t >> 5] = lmax;
    __syncthreads();
    float maxE = sRed[0];
#pragma unroll
    for (int i = 1; i < 16; i++) maxE = fmaxf(maxE, sRed[i]);

#pragma unroll
    for (int k = 0; k < 4; k++) {
        const int r = k * 512 + t;
        float sm = es[k] + maxE;
        float m  = fmaxf(sm, 0.2f * sm);
        float dd = ed[k] - maxE;
        g_AI2[(size_t)bh * NN + r] = make_float2(__expf(sm - m), __expf(0.2f * sm - m));
        g_E1[(size_t)bh * NN + r]  = __expf(dd);
        g_E2[(size_t)bh * NN + r]  = __expf(0.2f * dd);
    }
}

// ---------------- kernel 4: attention via mma.sync fp16 k16, 128-j chunks ----------------
// p = exp(LeakyReLU(s)-m) = max(A1*E1, A2*E2)  (exp monotone + LR = max(s,0.2s))
// -> no comparison needed; packed f32x2 products; adjacency mask via int AND.
__global__ __launch_bounds__(256) void k_attn(float* __restrict__ out) {
    __shared__ uint32_t sB[2][2048];      // 2 x 8KB fp16x2 words, fragment order, nb-XOR swizzled
    __shared__ float    sE1[2][128];
    __shared__ float    sE2[2][128];
    const int t    = threadIdx.x;
    const int lane = t & 31;
    const int wid  = t >> 5;
    const int g    = lane >> 2;
    const int tig  = lane & 3;
    const int bh   = blockIdx.y;
    const int b    = bh >> 3;
    const int h    = bh & 7;
    const int i0   = blockIdx.x * 128;
    const int r0   = i0 + wid * 16 + g;
    const int r1   = r0 + 8;

    const float2 ai0 = g_AI2[(size_t)bh * NN + r0];
    const float2 ai1 = g_AI2[(size_t)bh * NN + r1];
    const unsigned long long A10 = pk2(ai0.x, ai0.x), A20 = pk2(ai0.y, ai0.y);
    const unsigned long long A11 = pk2(ai1.x, ai1.x), A21 = pk2(ai1.y, ai1.y);
    float rs0 = 0.f, rs1 = 0.f;
    float acc[16];
#pragma unroll
    for (int i = 0; i < 16; i++) acc[i] = 0.f;

    const float4*   whp4 = (const float4*)(g_Wh + (size_t)bh * NN * DD);
    const float*    e1p  = g_E1 + (size_t)bh * NN;
    const float*    e2p  = g_E2 + (size_t)bh * NN;
    const unsigned* adjp = g_adj + (size_t)b * NW * NN;

    // staging geometry (per 64-j sub-chunk, done twice per 128-j chunk)
    const int sw_w  = t >> 6;            // 0..3
    const int sw_kp = (t >> 3) & 7;
    const int sw_q  = t & 7;
    const int sw_tg = sw_kp & 3;
    const int sw_hb = sw_kp >> 2;
    const int sw_nb = sw_q >> 1;
    const int sw_j  = sw_w * 16 + sw_kp * 2;
    const int sw_xs = sw_nb << 3;

    // ---- prologue: stage chunk 0 ----
    {
#pragma unroll
        for (int s = 0; s < 2; s++) {
            float4 v0 = whp4[(size_t)(s * 64 + sw_j) * 8 + sw_q];
            float4 v1 = whp4[(size_t)(s * 64 + sw_j + 1) * 8 + sw_q];
#pragma unroll
            for (int u = 0; u < 4; u++) {
                int dg  = (sw_q & 1) * 4 + u;
                int idx = ((s*4 + sw_w)*4 + sw_nb)*64
                        + (((dg*4 + sw_tg)*2 + sw_hb) ^ sw_xs);
                sB[0][idx] = h2pack((&v0.x)[u], (&v1.x)[u]);
            }
        }
        if (t < 32)             ((float4*)sE1[0])[t]      = ((const float4*)e1p)[t];
        else if (t < 64)        ((float4*)sE2[0])[t - 32] = ((const float4*)e2p)[t - 32];
    }
    unsigned aw0[4], aw1[4];
#pragma unroll
    for (int q = 0; q < 4; q++) {
        aw0[q] = adjp[(size_t)q * NN + r0];
        aw1[q] = adjp[(size_t)q * NN + r1];
    }
    __syncthreads();

    for (int c = 0; c < 16; c++) {
        const int buf = c & 1;
        const int cn  = (c + 1 < 16) ? c + 1 : 0;
        // ---- prefetch chunk cn ----
        float4 vB[2][2];
#pragma unroll
        for (int s = 0; s < 2; s++) {
            vB[s][0] = whp4[((size_t)cn * 128 + s * 64 + sw_j) * 8 + sw_q];
            vB[s][1] = whp4[((size_t)cn * 128 + s * 64 + sw_j + 1) * 8 + sw_q];
        }
        float4 vE = make_float4(0.f, 0.f, 0.f, 0.f);
        if (t < 32)      vE = ((const float4*)(e1p + cn * 128))[t];
        else if (t < 64) vE = ((const float4*)(e2p + cn * 128))[t - 32];
        unsigned nw0[4], nw1[4];
#pragma unroll
        for (int q = 0; q < 4; q++) {
            nw0[q] = adjp[(size_t)(cn * 4 + q) * NN + r0];
            nw1[q] = adjp[(size_t)(cn * 4 + q) * NN + r1];
        }

        // ---- inner: 8 k16 windows of 16 j ----
#pragma unroll
        for (int w = 0; w < 8; w++) {
            const int sh = (w & 1) * 16 + 2 * tig;
            const unsigned w0 = aw0[w >> 1] >> sh;
            const unsigned w1 = aw1[w >> 1] >> sh;
            const int p0i = (w * 8 + tig) * 2;
            unsigned long long E1a = *(const unsigned long long*)&sE1[buf][p0i];
            unsigned long long E2a = *(const unsigned long long*)&sE2[buf][p0i];
            unsigned long long E1b = *(const unsigned long long*)&sE1[buf][p0i + 8];
            unsigned long long E2b = *(const unsigned long long*)&sE2[buf][p0i + 8];

            // row 0
            float2 u = upk2(fmul2(A10, E1a)), v = upk2(fmul2(A20, E2a));
            float p00 = fmaxf(u.x, v.x), p01 = fmaxf(u.y, v.y);
            u = upk2(fmul2(A10, E1b)); v = upk2(fmul2(A20, E2b));
            float p02 = fmaxf(u.x, v.x), p03 = fmaxf(u.y, v.y);
            p00 = __uint_as_float(__float_as_uint(p00) & (0u - ( w0        & 1u)));
            p01 = __uint_as_float(__float_as_uint(p01) & (0u - ((w0 >> 1)  & 1u)));
            p02 = __uint_as_float(__float_as_uint(p02) & (0u - ((w0 >> 8)  & 1u)));
            p03 = __uint_as_float(__float_as_uint(p03) & (0u - ((w0 >> 9)  & 1u)));
            rs0 += (p00 + p01) + (p02 + p03);
            uint32_t a0 = h2pack(p00, p01), a2 = h2pack(p02, p03);

            // row 1
            u = upk2(fmul2(A11, E1a)); v = upk2(fmul2(A21, E2a));
            float p10 = fmaxf(u.x, v.x), p11 = fmaxf(u.y, v.y);
            u = upk2(fmul2(A11, E1b)); v = upk2(fmul2(A21, E2b));
            float p12 = fmaxf(u.x, v.x), p13 = fmaxf(u.y, v.y);
            p10 = __uint_as_float(__float_as_uint(p10) & (0u - ( w1        & 1u)));
            p11 = __uint_as_float(__float_as_uint(p11) & (0u - ((w1 >> 1)  & 1u)));
            p12 = __uint_as_float(__float_as_uint(p12) & (0u - ((w1 >> 8)  & 1u)));
            p13 = __uint_as_float(__float_as_uint(p13) & (0u - ((w1 >> 9)  & 1u)));
            rs1 += (p10 + p11) + (p12 + p13);
            uint32_t a1 = h2pack(p10, p11), a3 = h2pack(p12, p13);

#pragma unroll
            for (int nb = 0; nb < 4; nb++) {
                uint2 bb2 = *(const uint2*)&sB[buf][(w*4 + nb)*64 + ((lane*2) ^ (nb << 3))];
                mma_f16(acc + nb * 4, a0, a1, a2, a3, bb2.x, bb2.y);
            }
        }

        // ---- stage chunk cn into the other buffer ----
        const int nbuf = buf ^ 1;
#pragma unroll
        for (int s = 0; s < 2; s++) {
#pragma unroll
            for (int u2 = 0; u2 < 4; u2++) {
                int dg  = (sw_q & 1) * 4 + u2;
                int idx = ((s*4 + sw_w)*4 + sw_nb)*64
                        + (((dg*4 + sw_tg)*2 + sw_hb) ^ sw_xs);
                sB[nbuf][idx] = h2pack((&vB[s][0].x)[u2], (&vB[s][1].x)[u2]);
            }
        }
        if (t < 32)      ((float4*)sE1[nbuf])[t]      = vE;
        else if (t < 64) ((float4*)sE2[nbuf])[t - 32] = vE;
#pragma unroll
        for (int q = 0; q < 4; q++) { aw0[q] = nw0[q]; aw1[q] = nw1[q]; }
        __syncthreads();
    }

    // ---- epilogue: quad-reduce row sums, normalize, store ----
    rs0 += __shfl_xor_sync(0xffffffffu, rs0, 1);
    rs0 += __shfl_xor_sync(0xffffffffu, rs0, 2);
    rs1 += __shfl_xor_sync(0xffffffffu, rs1, 1);
    rs1 += __shfl_xor_sync(0xffffffffu, rs1, 2);
    const float inv0 = 1.0f / rs0;
    const float inv1 = 1.0f / rs1;

    float* o0 = out + ((size_t)(b * NN + r0)) * (HH * DD) + h * DD + tig * 2;
    float* o1 = out + ((size_t)(b * NN + r1)) * (HH * DD) + h * DD + tig * 2;
#pragma unroll
    for (int nb = 0; nb < 4; nb++) {
        *(float2*)(o0 + nb * 8) = make_float2(acc[nb*4 + 0] * inv0, acc[nb*4 + 1] * inv0);
        *(float2*)(o1 + nb * 8) = make_float2(acc[nb*4 + 2] * inv1, acc[nb*4 + 3] * inv1);
    }
}

// ---------------- launch ----------------
extern "C" void kernel_launch(void* const* d_in, const int* in_sizes, int n_in,
                              void* d_out, int out_size) {
    const float* x   = (const float*)d_in[0];
    const int*   adj = (const int*)  d_in[1];
    const float* W   = (const float*)d_in[2];
    const float* a   = (const float*)d_in[3];
    float* out = (float*)d_out;

    k_pack <<<2048, 256>>>(adj);
    k_gemm1<<<dim3(2, 64), 256>>>(x, W);
    k_ee   <<<BB*HH, 512>>>(a);
    k_attn <<<dim3(NN/128, BB*HH), 256>>>(out);
}

// round 14
// speedup vs baseline: 3.1010x; 1.0015x over previous
#include <cuda_runtime.h>
#include <cuda_bf16.h>
#include <cstdint>

#define BB  4
#define NN  2048
#define FIN 256
#define HH  8
#define DD  32
#define NW  (NN/32)   // 64 adj words per row

// ---------------- device scratch (no allocations allowed) ----------------
__device__ float    g_Wh[BB*HH*NN*DD];       // [b][h][n][d]  8.4MB
__device__ float2   g_AI2[BB*HH*NN];         // (A1, A2) per row i
__device__ uint32_t g_E12[BB*HH*(NN/2)*2];   // per j-pair: {E1 f16x2, E2 f16x2} interleaved
__device__ unsigned g_adj[BB*NN*NW];         // packed adjacency bits, TRANSPOSED [b][jw][i]

// ---------------- mma.sync / packed helpers (portable PTX) ----------------
__device__ __forceinline__ void mma_bf16(float* c,
                                         uint32_t a0, uint32_t a1, uint32_t a2, uint32_t a3,
                                         uint32_t b0, uint32_t b1) {
    asm volatile(
        "mma.sync.aligned.m16n8k16.row.col.f32.bf16.bf16.f32 "
        "{%0,%1,%2,%3}, {%4,%5,%6,%7}, {%8,%9}, {%0,%1,%2,%3};"
        : "+f"(c[0]), "+f"(c[1]), "+f"(c[2]), "+f"(c[3])
        : "r"(a0), "r"(a1), "r"(a2), "r"(a3), "r"(b0), "r"(b1));
}
__device__ __forceinline__ void mma_f16(float* c,
                                        uint32_t a0, uint32_t a1, uint32_t a2, uint32_t a3,
                                        uint32_t b0, uint32_t b1) {
    asm volatile(
        "mma.sync.aligned.m16n8k16.row.col.f32.f16.f16.f32 "
        "{%0,%1,%2,%3}, {%4,%5,%6,%7}, {%8,%9}, {%0,%1,%2,%3};"
        : "+f"(c[0]), "+f"(c[1]), "+f"(c[2]), "+f"(c[3])
        : "r"(a0), "r"(a1), "r"(a2), "r"(a3), "r"(b0), "r"(b1));
}
__device__ __forceinline__ uint32_t bfpack(float lo, float hi) {
    uint32_t r;
    asm("cvt.rn.bf16x2.f32 %0, %1, %2;" : "=r"(r) : "f"(hi), "f"(lo));
    return r;
}
__device__ __forceinline__ uint32_t h2pack(float lo, float hi) {
    uint32_t r;
    asm("cvt.rn.f16x2.f32 %0, %1, %2;" : "=r"(r) : "f"(hi), "f"(lo));
    return r;
}
__device__ __forceinline__ float bfround(float v) {
    return __bfloat162float(__float2bfloat16(v));
}
__device__ __forceinline__ uint32_t hmul2(uint32_t a, uint32_t b) {
    uint32_t r;
    asm("mul.f16x2 %0, %1, %2;" : "=r"(r) : "r"(a), "r"(b));
    return r;
}
__device__ __forceinline__ uint32_t hmax2(uint32_t a, uint32_t b) {
    uint32_t r;
    asm("max.f16x2 %0, %1, %2;" : "=r"(r) : "r"(a), "r"(b));
    return r;
}
// mask word for adjacency bits k,k+1: 0xFFFF per set halfword
__device__ __forceinline__ uint32_t mask2(uint32_t word, int k) {
    uint32_t t0, t1;
    asm("bfe.u32 %0, %1, %2, 1;" : "=r"(t0) : "r"(word), "r"(k));
    asm("bfe.u32 %0, %1, %2, 1;" : "=r"(t1) : "r"(word), "r"(k + 1));
    return t0 * 0x0000FFFFu + t1 * 0xFFFF0000u;
}

// ---------------- kernel 1: pack adjacency to bits (transposed) ----------------
__global__ __launch_bounds__(256) void k_pack(const int* __restrict__ adj) {
    const int nwarps = (gridDim.x * blockDim.x) >> 5;
    const int wid    = (blockIdx.x * blockDim.x + threadIdx.x) >> 5;
    const int lane   = threadIdx.x & 31;
    const int total  = BB*NN*NW;
    for (int w = wid; w < total; w += nwarps) {
        int v = adj[(size_t)w * 32 + lane];
        unsigned m = __ballot_sync(0xffffffffu, v != 0);
        if (lane == 0) {
            int b  = w / (NN*NW);
            int r  = w - b * (NN*NW);
            int i  = r / NW;
            int jw = r - i * NW;
            g_adj[((size_t)b * NW + jw) * NN + i] = m;
        }
    }
}

// ---------------- kernel 2: Wh = x @ W via 3xBF16 mma.sync (near-fp32) ----------------
__global__ __launch_bounds__(256) void k_gemm1(const float* __restrict__ x,
                                               const float* __restrict__ W) {
    __shared__ uint32_t sAh[128*12], sAl[128*12];    // [row][k2 pad 12] bf16x2 words
    __shared__ uint32_t sBh[8*136],  sBl[8*136];     // [k2][col128 pad 136]
    const int t    = threadIdx.x;
    const int lane = t & 31;
    const int wid  = t >> 5;
    const int g    = lane >> 2;
    const int tig  = lane & 3;
    const int wy   = wid & 3;
    const int wx   = wid >> 2;
    const int rb   = blockIdx.y * 128;
    const int cb   = blockIdx.x * 128;

    const int row_a = t >> 1;
    const int kb_a  = (t & 1) * 8;
    const int col_b = t & 127;
    const int kb_b  = (t >> 7) * 8;
    const int col_g = cb + col_b;
    const float* wp = W + (size_t)(col_g >> 5) * (FIN*DD) + (col_g & 31);
    const float* xp = x + (size_t)(rb + row_a) * FIN + kb_a;

    float acc[2][8][4];
#pragma unroll
    for (int mi = 0; mi < 2; mi++)
#pragma unroll
        for (int nb = 0; nb < 8; nb++)
#pragma unroll
            for (int q = 0; q < 4; q++) acc[mi][nb][q] = 0.f;

    float4 va0 = *(const float4*)(xp);
    float4 va1 = *(const float4*)(xp + 4);
    float  vb[8];
#pragma unroll
    for (int i = 0; i < 8; i++) vb[i] = wp[(size_t)(kb_b + i) * DD];

    for (int ch = 0; ch < 16; ch++) {
        __syncthreads();
        {
            float av[8] = {va0.x, va0.y, va0.z, va0.w, va1.x, va1.y, va1.z, va1.w};
#pragma unroll
            for (int i = 0; i < 4; i++) {
                float v0 = av[2*i], v1 = av[2*i+1];
                float h0 = bfround(v0), h1 = bfround(v1);
                sAh[row_a * 12 + (kb_a >> 1) + i] = bfpack(h0, h1);
                sAl[row_a * 12 + (kb_a >> 1) + i] = bfpack(v0 - h0, v1 - h1);
            }
#pragma unroll
            for (int i = 0; i < 4; i++) {
                float v0 = vb[2*i], v1 = vb[2*i+1];
                float h0 = bfround(v0), h1 = bfround(v1);
                sBh[((kb_b >> 1) + i) * 136 + col_b] = bfpack(h0, h1);
                sBl[((kb_b >> 1) + i) * 136 + col_b] = bfpack(v0 - h0, v1 - h1);
            }
        }
        __syncthreads();
        if (ch < 15) {
            const int kc = (ch + 1) * 16;
            va0 = *(const float4*)(xp + kc);
            va1 = *(const float4*)(xp + kc + 4);
#pragma unroll
            for (int i = 0; i < 8; i++) vb[i] = wp[(size_t)(kc + kb_b + i) * DD];
        }
        uint32_t ah[2][4], al[2][4];
#pragma unroll
        for (int mi = 0; mi < 2; mi++) {
            int base = (wy*32 + mi*16 + g) * 12 + tig;
            ah[mi][0] = sAh[base];     ah[mi][1] = sAh[base + 96];
            ah[mi][2] = sAh[base + 4]; ah[mi][3] = sAh[base + 100];
            al[mi][0] = sAl[base];     al[mi][1] = sAl[base + 96];
            al[mi][2] = sAl[base + 4]; al[mi][3] = sAl[base + 100];
        }
#pragma unroll
        for (int nb = 0; nb < 8; nb++) {
            int colb = wx*64 + nb*8 + g;
            uint32_t bh0 = sBh[tig * 136 + colb], bh1 = sBh[(tig + 4) * 136 + colb];
            uint32_t bl0 = sBl[tig * 136 + colb], bl1 = sBl[(tig + 4) * 136 + colb];
#pragma unroll
            for (int mi = 0; mi < 2; mi++) {
                float* c = acc[mi][nb];
                mma_bf16(c, ah[mi][0], ah[mi][1], ah[mi][2], ah[mi][3], bh0, bh1);
                mma_bf16(c, al[mi][0], al[mi][1], al[mi][2], al[mi][3], bh0, bh1);
                mma_bf16(c, ah[mi][0], ah[mi][1], ah[mi][2], ah[mi][3], bl0, bl1);
            }
        }
    }

#pragma unroll
    for (int mi = 0; mi < 2; mi++) {
        int r0 = rb + wy*32 + mi*16 + g;
        int r1 = r0 + 8;
        int b0 = r0 >> 11, n0 = r0 & (NN-1);
        int b1 = r1 >> 11, n1 = r1 & (NN-1);
#pragma unroll
        for (int nb = 0; nb < 8; nb++) {
            int col = cb + wx*64 + nb*8 + tig*2;
            int h = col >> 5, d = col & 31;
            float* o0 = g_Wh + ((size_t)(b0*HH + h) * NN + n0) * DD + d;
            float* o1 = g_Wh + ((size_t)(b1*HH + h) * NN + n1) * DD + d;
            *(float2*)o0 = make_float2(acc[mi][nb][0], acc[mi][nb][1]);
            *(float2*)o1 = make_float2(acc[mi][nb][2], acc[mi][nb][3]);
        }
    }
}

// ---------------- kernel 3: fused e/max/exp — one CTA per (b,h) ----------------
// Emits A1,A2 (f32) per row and E1,E2 packed as f16x2 j-pairs (interleaved).
__global__ __launch_bounds__(512) void k_ee(const float* __restrict__ a) {
    __shared__ float sA[64];
    __shared__ float sRed[16];
    const int bh = blockIdx.x;
    const int h  = bh & 7;
    const int t  = threadIdx.x;
    if (t < 16) ((float4*)sA)[t] = ((const float4*)(a + h * 64))[t];
    __syncthreads();

    float es[4], ed[4];
    float lmax = -1e30f;
    const float* whb = g_Wh + (size_t)bh * NN * DD;
#pragma unroll
    for (int k = 0; k < 4; k++) {
        const int r = k * 512 + t;
        const float4* wr = (const float4*)(whb + (size_t)r * DD);
        float s0 = 0.f, s1 = 0.f;
#pragma unroll
        for (int q = 0; q < 8; q++) {
            float4 w  = wr[q];
            float4 as = ((const float4*)sA)[q];
            float4 ad = ((const float4*)sA)[8 + q];
            s0 += w.x*as.x + w.y*as.y + w.z*as.z + w.w*as.w;
            s1 += w.x*ad.x + w.y*ad.y + w.z*ad.z + w.w*ad.w;
        }
        es[k] = s0; ed[k] = s1;
        lmax = fmaxf(lmax, s1);
    }
#pragma unroll
    for (int o = 16; o; o >>= 1)
        lmax = fmaxf(lmax, __shfl_xor_sync(0xffffffffu, lmax, o));
    if ((t & 31) == 0) sRed[t >> 5] = lmax;
    __syncthreads();
    float maxE = sRed[0];
#pragma unroll
    for (int i = 1; i < 16; i++) maxE = fmaxf(maxE, sRed[i]);

#pragma unroll
    for (int k = 0; k < 4; k++) {
        const int r = k * 512 + t;
        float sm = es[k] + maxE;
        float m  = fmaxf(sm, 0.2f * sm);
        float dd = ed[k] - maxE;
        g_AI2[(size_t)bh * NN + r] = make_float2(__expf(sm - m), __expf(0.2f * sm - m));
        float E1 = __expf(dd);
        float E2 = __expf(0.2f * dd);
        float o1 = __shfl_down_sync(0xffffffffu, E1, 1);
        float o2 = __shfl_down_sync(0xffffffffu, E2, 1);
        if ((t & 1) == 0) {
            const size_t p = (size_t)bh * (NN/2) + (r >> 1);
            g_E12[p * 2]     = h2pack(E1, o1);
            g_E12[p * 2 + 1] = h2pack(E2, o2);
        }
    }
}

// ---------------- kernel 4: attention — fully packed fp16 p, rowsum via ones-mma ----------------
// p(pair) = max.f16x2(A1h*E1pair, A2h*E2pair) & mask32(adjacency bits)
__global__ __launch_bounds__(256) void k_attn(float* __restrict__ out) {
    __shared__ uint32_t sB[2][2048];      // 2 x 8KB fp16x2 B words, fragment order, nb-XOR swizzled
    __shared__ uint32_t sE12[2][128];     // per chunk: 64 j-pairs x {E1,E2}
    const int t    = threadIdx.x;
    const int lane = t & 31;
    const int wid  = t >> 5;
    const int g    = lane >> 2;
    const int tig  = lane & 3;
    const int bh   = blockIdx.y;
    const int b    = bh >> 3;
    const int h    = bh & 7;
    const int i0   = blockIdx.x * 128;
    const int r0   = i0 + wid * 16 + g;
    const int r1   = r0 + 8;
    const uint32_t ONES2 = 0x3C003C00u;   // (1.0h, 1.0h)

    const float2 ai0 = g_AI2[(size_t)bh * NN + r0];
    const float2 ai1 = g_AI2[(size_t)bh * NN + r1];
    const uint32_t A1h0 = h2pack(ai0.x, ai0.x), A2h0 = h2pack(ai0.y, ai0.y);
    const uint32_t A1h1 = h2pack(ai1.x, ai1.x), A2h1 = h2pack(ai1.y, ai1.y);
    float acc[16];
    float accs[4];
#pragma unroll
    for (int i = 0; i < 16; i++) acc[i] = 0.f;
#pragma unroll
    for (int i = 0; i < 4; i++) accs[i] = 0.f;

    const float4*   whp4 = (const float4*)(g_Wh + (size_t)bh * NN * DD);
    const uint32_t* e12p = g_E12 + (size_t)bh * NN;          // NN words per (b,h)
    const unsigned* adjp = g_adj + (size_t)b * NW * NN;

    // B staging geometry (per 64-j sub-chunk, done twice per 128-j chunk)
    const int sw_w  = t >> 6;
    const int sw_kp = (t >> 3) & 7;
    const int sw_q  = t & 7;
    const int sw_tg = sw_kp & 3;
    const int sw_hb = sw_kp >> 2;
    const int sw_nb = sw_q >> 1;
    const int sw_j  = sw_w * 16 + sw_kp * 2;
    const int sw_xs = sw_nb << 3;

    // ---- prologue: stage chunk 0 ----
    {
#pragma unroll
        for (int s = 0; s < 2; s++) {
            float4 v0 = whp4[(size_t)(s * 64 + sw_j) * 8 + sw_q];
            float4 v1 = whp4[(size_t)(s * 64 + sw_j + 1) * 8 + sw_q];
#pragma unroll
            for (int u = 0; u < 4; u++) {
                int dg  = (sw_q & 1) * 4 + u;
                int idx = ((s*4 + sw_w)*4 + sw_nb)*64
                        + (((dg*4 + sw_tg)*2 + sw_hb) ^ sw_xs);
                sB[0][idx] = h2pack((&v0.x)[u], (&v1.x)[u]);
            }
        }
        if (t < 32) ((uint4*)sE12[0])[t] = ((const uint4*)e12p)[t];
    }
    unsigned aw0[4], aw1[4];
#pragma unroll
    for (int q = 0; q < 4; q++) {
        aw0[q] = adjp[(size_t)q * NN + r0];
        aw1[q] = adjp[(size_t)q * NN + r1];
    }
    __syncthreads();

    for (int c = 0; c < 16; c++) {
        const int buf = c & 1;
        const int cn  = (c + 1 < 16) ? c + 1 : 0;
        // ---- prefetch chunk cn ----
        float4 vB[2][2];
#pragma unroll
        for (int s = 0; s < 2; s++) {
            vB[s][0] = whp4[((size_t)cn * 128 + s * 64 + sw_j) * 8 + sw_q];
            vB[s][1] = whp4[((size_t)cn * 128 + s * 64 + sw_j + 1) * 8 + sw_q];
        }
        uint4 vE = make_uint4(0u, 0u, 0u, 0u);
        if (t < 32) vE = ((const uint4*)(e12p + cn * 128))[t];
        unsigned nw0[4], nw1[4];
#pragma unroll
        for (int q = 0; q < 4; q++) {
            nw0[q] = adjp[(size_t)(cn * 4 + q) * NN + r0];
            nw1[q] = adjp[(size_t)(cn * 4 + q) * NN + r1];
        }

        // ---- inner: 8 k16 windows of 16 j ----
#pragma unroll
        for (int w = 0; w < 8; w++) {
            const uint32_t wd0 = aw0[w >> 1], wd1 = aw1[w >> 1];
            const int kb = (w & 1) * 16 + 2 * tig;
            const uint32_t m0a = mask2(wd0, kb),     m0b = mask2(wd0, kb + 8);
            const uint32_t m1a = mask2(wd1, kb),     m1b = mask2(wd1, kb + 8);
            const int pi = (w * 8 + tig) * 2;
            uint2 Ea = *(const uint2*)&sE12[buf][pi];       // {E1 pair, E2 pair}
            uint2 Eb = *(const uint2*)&sE12[buf][pi + 8];   // pair +4
            uint32_t a0 = hmax2(hmul2(A1h0, Ea.x), hmul2(A2h0, Ea.y)) & m0a;
            uint32_t a1 = hmax2(hmul2(A1h1, Ea.x), hmul2(A2h1, Ea.y)) & m1a;
            uint32_t a2 = hmax2(hmul2(A1h0, Eb.x), hmul2(A2h0, Eb.y)) & m0b;
            uint32_t a3 = hmax2(hmul2(A1h1, Eb.x), hmul2(A2h1, Eb.y)) & m1b;
#pragma unroll
            for (int nb = 0; nb < 4; nb++) {
                uint2 bb2 = *(const uint2*)&sB[buf][(w*4 + nb)*64 + ((lane*2) ^ (nb << 3))];
                mma_f16(acc + nb * 4, a0, a1, a2, a3, bb2.x, bb2.y);
            }
            mma_f16(accs, a0, a1, a2, a3, ONES2, ONES2);    // rowsums
        }

        // ---- stage chunk cn into the other buffer ----
        const int nbuf = buf ^ 1;
#pragma unroll
        for (int s = 0; s < 2; s++) {
#pragma unroll
            for (int u2 = 0; u2 < 4; u2++) {
                int dg  = (sw_q & 1) * 4 + u2;
                int idx = ((s*4 + sw_w)*4 + sw_nb)*64
                        + (((dg*4 + sw_tg)*2 + sw_hb) ^ sw_xs);
                sB[nbuf][idx] = h2pack((&vB[s][0].x)[u2], (&vB[s][1].x)[u2]);
            }
        }
        if (t < 32) ((uint4*)sE12[nbuf])[t] = vE;
#pragma unroll
        for (int q = 0; q < 4; q++) { aw0[q] = nw0[q]; aw1[q] = nw1[q]; }
        __syncthreads();
    }

    // ---- epilogue: normalize by mma-computed rowsums, store ----
    const float inv0 = 1.0f / accs[0];
    const float inv1 = 1.0f / accs[2];

    float* o0 = out + ((size_t)(b * NN + r0)) * (HH * DD) + h * DD + tig * 2;
    float* o1 = out + ((size_t)(b * NN + r1)) * (HH * DD) + h * DD + tig * 2;
#pragma unroll
    for (int nb = 0; nb < 4; nb++) {
        *(float2*)(o0 + nb * 8) = make_float2(acc[nb*4 + 0] * inv0, acc[nb*4 + 1] * inv0);
        *(float2*)(o1 + nb * 8) = make_float2(acc[nb*4 + 2] * inv1, acc[nb*4 + 3] * inv1);
    }
}

// ---------------- launch ----------------
extern "C" void kernel_launch(void* const* d_in, const int* in_sizes, int n_in,
                              void* d_out, int out_size) {
    const float* x   = (const float*)d_in[0];
    const int*   adj = (const int*)  d_in[1];
    const float* W   = (const float*)d_in[2];
    const float* a   = (const float*)d_in[3];
    float* out = (float*)d_out;

    k_pack <<<2048, 256>>>(adj);
    k_gemm1<<<dim3(2, 64), 256>>>(x, W);
    k_ee   <<<BB*HH, 512>>>(a);
    k_attn <<<dim3(NN/128, BB*HH), 256>>>(out);
}